// round 2
// baseline (speedup 1.0000x reference)
#include <cuda_runtime.h>
#include <math.h>

#define BB 2
#define SS 2048
#define DD 1024
#define HH 16
#define HD 64
#define MTOK (BB*SS)   // 4096

// Scratch (allocation-free rule: __device__ globals)
__device__ float g_qkv[BB*SS*3*DD];   // [B*S, 3D]
__device__ float g_attn[BB*SS*DD];    // [B*S, D]

// ---------------------------------------------------------------------------
// C[M,N] = A[M,K] @ W[N,K]^T + bias[N]   (torch Linear: y = x W^T + b)
// 64x64 block tile, 256 threads, 4x4 register tile per thread, BK=16.
// ---------------------------------------------------------------------------
__global__ void gemm_nt_kernel(const float* __restrict__ A,
                               const float* __restrict__ W,
                               const float* __restrict__ bias,
                               float* __restrict__ C,
                               int M, int N, int K) {
    __shared__ float As[64][17];
    __shared__ float Ws[64][17];
    const int tid = threadIdx.x;
    const int tx = tid & 15;
    const int ty = tid >> 4;
    const int row0 = blockIdx.y * 64;
    const int col0 = blockIdx.x * 64;

    float acc[4][4] = {};

    for (int k0 = 0; k0 < K; k0 += 16) {
        // 64x16 tiles, 1024 elems, 256 threads -> 4 each
        #pragma unroll
        for (int t = tid; t < 64*16; t += 256) {
            int r = t >> 4, c = t & 15;
            As[r][c] = A[(size_t)(row0 + r) * K + k0 + c];
            Ws[r][c] = W[(size_t)(col0 + r) * K + k0 + c];
        }
        __syncthreads();
        #pragma unroll
        for (int kk = 0; kk < 16; kk++) {
            float a[4], w[4];
            #pragma unroll
            for (int i = 0; i < 4; i++) a[i] = As[ty*4 + i][kk];
            #pragma unroll
            for (int j = 0; j < 4; j++) w[j] = Ws[tx*4 + j][kk];
            #pragma unroll
            for (int i = 0; i < 4; i++)
                #pragma unroll
                for (int j = 0; j < 4; j++)
                    acc[i][j] += a[i] * w[j];
        }
        __syncthreads();
    }

    #pragma unroll
    for (int i = 0; i < 4; i++) {
        int r = row0 + ty*4 + i;
        #pragma unroll
        for (int j = 0; j < 4; j++) {
            int c = col0 + tx*4 + j;
            C[(size_t)r * N + c] = acc[i][j] + bias[c];
        }
    }
}

// ---------------------------------------------------------------------------
// Flash-attention style causal MHA, fp32.
// One CTA = (batch b, head h, 64-row q tile). 256 threads (16x16), each owns
// a 4x4 fragment of the 64x64 S tile and of the 64x64 O accumulator.
// ---------------------------------------------------------------------------
struct AttnSmem {
    float Qs[64][65];
    float Ks[64][65];
    float Vs[64][65];
    float Ps[64][65];
    float m_s[64];
    float l_s[64];
    float redm[64][16];
    float reds[64][16];
};

__global__ void attn_kernel(const float* __restrict__ qkv,
                            float* __restrict__ outp) {
    extern __shared__ char smem_raw[];
    AttnSmem& sm = *reinterpret_cast<AttnSmem*>(smem_raw);

    const int qt = blockIdx.x;   // 0..31
    const int h  = blockIdx.y;   // 0..15
    const int b  = blockIdx.z;   // 0..1
    const int tid = threadIdx.x;
    const int tx = tid & 15;
    const int ty = tid >> 4;
    const int q0 = qt * 64;

    // Load Q tile [64 x 64]
    for (int t = tid; t < 64*64; t += 256) {
        int r = t >> 6, d = t & 63;
        sm.Qs[r][d] = qkv[(size_t)(b*SS + q0 + r) * (3*DD) + h*HD + d];
    }
    if (tid < 64) { sm.m_s[tid] = -1e30f; sm.l_s[tid] = 0.0f; }

    float acc[4][4] = {};

    for (int kt = 0; kt <= qt; kt++) {
        const int k0 = kt * 64;
        __syncthreads();   // prev-iter Ks/Vs/Ps reads done; Q load done (iter 0)

        // Load K and V tiles
        for (int t = tid; t < 64*64; t += 256) {
            int r = t >> 6, d = t & 63;
            size_t base = (size_t)(b*SS + k0 + r) * (3*DD) + h*HD + d;
            sm.Ks[r][d] = qkv[base + DD];
            sm.Vs[r][d] = qkv[base + 2*DD];
        }
        __syncthreads();

        // S = Q K^T (4x4 fragment per thread)
        float s[4][4] = {};
        #pragma unroll 8
        for (int d = 0; d < 64; d++) {
            float a[4], kf[4];
            #pragma unroll
            for (int i = 0; i < 4; i++) a[i] = sm.Qs[ty*4 + i][d];
            #pragma unroll
            for (int j = 0; j < 4; j++) kf[j] = sm.Ks[tx*4 + j][d];
            #pragma unroll
            for (int i = 0; i < 4; i++)
                #pragma unroll
                for (int j = 0; j < 4; j++)
                    s[i][j] += a[i] * kf[j];
        }

        // scale + causal mask + local row max
        #pragma unroll
        for (int i = 0; i < 4; i++) {
            int qg = q0 + ty*4 + i;
            float lm = -1e30f;
            #pragma unroll
            for (int j = 0; j < 4; j++) {
                int kg = k0 + tx*4 + j;
                float v = (kg <= qg) ? s[i][j] * 0.125f : -1e30f;
                s[i][j] = v;
                lm = fmaxf(lm, v);
            }
            sm.redm[ty*4 + i][tx] = lm;
        }
        __syncthreads();

        // online softmax update
        float scale_i[4], newm[4];
        #pragma unroll
        for (int i = 0; i < 4; i++) {
            int row = ty*4 + i;
            float tm = -1e30f;
            #pragma unroll
            for (int t2 = 0; t2 < 16; t2++) tm = fmaxf(tm, sm.redm[row][t2]);
            float om = sm.m_s[row];
            float nm = fmaxf(om, tm);
            newm[i] = nm;
            scale_i[i] = __expf(om - nm);
            float ls = 0.0f;
            #pragma unroll
            for (int j = 0; j < 4; j++) {
                float p = __expf(s[i][j] - nm);
                sm.Ps[row][tx*4 + j] = p;
                ls += p;
            }
            sm.reds[row][tx] = ls;
            #pragma unroll
            for (int j = 0; j < 4; j++) acc[i][j] *= scale_i[i];
        }
        __syncthreads();

        if (tx == 0) {
            #pragma unroll
            for (int i = 0; i < 4; i++) {
                int row = ty*4 + i;
                float tot = 0.0f;
                #pragma unroll
                for (int t2 = 0; t2 < 16; t2++) tot += sm.reds[row][t2];
                sm.l_s[row] = sm.l_s[row] * scale_i[i] + tot;
                sm.m_s[row] = newm[i];
            }
        }

        // O += P @ V
        #pragma unroll 8
        for (int c = 0; c < 64; c++) {
            float p[4], v[4];
            #pragma unroll
            for (int i = 0; i < 4; i++) p[i] = sm.Ps[ty*4 + i][c];
            #pragma unroll
            for (int j = 0; j < 4; j++) v[j] = sm.Vs[c][tx*4 + j];
            #pragma unroll
            for (int i = 0; i < 4; i++)
                #pragma unroll
                for (int j = 0; j < 4; j++)
                    acc[i][j] += p[i] * v[j];
        }
    }
    __syncthreads();   // final l_s writes visible

    // normalize and store to [B, S, H*Hd] layout
    #pragma unroll
    for (int i = 0; i < 4; i++) {
        int row = ty*4 + i;
        float inv = 1.0f / sm.l_s[row];
        #pragma unroll
        for (int j = 0; j < 4; j++) {
            outp[(size_t)(b*SS + q0 + row) * DD + h*HD + tx*4 + j] = acc[i][j] * inv;
        }
    }
}

// ---------------------------------------------------------------------------
extern "C" void kernel_launch(void* const* d_in, const int* in_sizes, int n_in,
                              void* d_out, int out_size) {
    const float* x     = (const float*)d_in[0];
    const float* W_qkv = (const float*)d_in[1];
    const float* b_qkv = (const float*)d_in[2];
    const float* W_out = (const float*)d_in[3];
    const float* b_out = (const float*)d_in[4];
    float* out = (float*)d_out;

    float *qkv_ptr = nullptr, *attn_ptr = nullptr;
    cudaGetSymbolAddress((void**)&qkv_ptr, g_qkv);
    cudaGetSymbolAddress((void**)&attn_ptr, g_attn);

    cudaFuncSetAttribute(attn_kernel,
                         cudaFuncAttributeMaxDynamicSharedMemorySize,
                         (int)sizeof(AttnSmem));

    // 1) QKV projection: [4096,1024] @ [3072,1024]^T -> [4096,3072]
    gemm_nt_kernel<<<dim3(3*DD/64, MTOK/64), 256>>>(x, W_qkv, b_qkv, qkv_ptr,
                                                    MTOK, 3*DD, DD);

    // 2) causal attention -> [B*S, D]
    attn_kernel<<<dim3(SS/64, HH, BB), 256, sizeof(AttnSmem)>>>(qkv_ptr, attn_ptr);

    // 3) output projection: [4096,1024] @ [1024,1024]^T -> [4096,1024]
    gemm_nt_kernel<<<dim3(DD/64, MTOK/64), 256>>>(attn_ptr, W_out, b_out, out,
                                                  MTOK, DD, DD);
}

// round 3
// speedup vs baseline: 1.5596x; 1.5596x over previous
#include <cuda_runtime.h>
#include <cuda_bf16.h>
#include <mma.h>
#include <math.h>

using namespace nvcuda;

#define BB 2
#define SS 2048
#define DD 1024
#define HH 16
#define HD 64
#define MTOK (BB*SS)   // 4096

// Scratch (allocation-free rule: __device__ globals)
__device__ float g_qkv[BB*SS*3*DD];   // [B*S, 3D]  (NO bias; folded into attention)
__device__ float g_attn[BB*SS*DD];    // [B*S, D]

// ---------------------------------------------------------------------------
// C[M,N] = A[M,K] @ W[N,K]^T   via 3-term bf16-split tensor-core MMA.
// x = hi + lo (bf16 each);  A*B ≈ Ah*Bh + Ah*Bl + Al*Bh  (fp32 accumulate)
// CTA tile 128x128, BK=32, 8 warps each computing 32x64.
// ---------------------------------------------------------------------------
#define BK 32
#define ASTR 40   // smem row stride (bf16 elems), multiple of 8

__global__ __launch_bounds__(256)
void gemm_bf16x3_kernel(const float* __restrict__ A,
                        const float* __restrict__ W,
                        float* __restrict__ C,
                        int M, int N, int K) {
    __shared__ __nv_bfloat16 Ah[128][ASTR];
    __shared__ __nv_bfloat16 Al[128][ASTR];
    __shared__ __nv_bfloat16 Bh[128][ASTR];
    __shared__ __nv_bfloat16 Bl[128][ASTR];

    const int tid = threadIdx.x;
    const int warp = tid >> 5;
    const int wr = warp >> 1;          // 0..3  -> rows warp tile (32 rows)
    const int wc = warp & 1;           // 0..1  -> cols warp tile (64 cols)
    const int row0 = blockIdx.y * 128;
    const int col0 = blockIdx.x * 128;

    wmma::fragment<wmma::accumulator, 16, 16, 16, float> acc[2][4];
    #pragma unroll
    for (int i = 0; i < 2; i++)
        #pragma unroll
        for (int j = 0; j < 4; j++)
            wmma::fill_fragment(acc[i][j], 0.0f);

    for (int k0 = 0; k0 < K; k0 += BK) {
        // Stage A and B tiles as bf16 hi/lo. 128x32 floats each = 1024 float4.
        #pragma unroll
        for (int t = tid; t < 1024; t += 256) {
            int r = t >> 3, c4 = (t & 7) * 4;
            float4 va = *reinterpret_cast<const float4*>(&A[(size_t)(row0 + r) * K + k0 + c4]);
            float4 vb = *reinterpret_cast<const float4*>(&W[(size_t)(col0 + r) * K + k0 + c4]);
            #pragma unroll
            for (int u = 0; u < 4; u++) {
                float fa = (&va.x)[u];
                __nv_bfloat16 ha = __float2bfloat16_rn(fa);
                Ah[r][c4 + u] = ha;
                Al[r][c4 + u] = __float2bfloat16_rn(fa - __bfloat162float(ha));
                float fb = (&vb.x)[u];
                __nv_bfloat16 hb = __float2bfloat16_rn(fb);
                Bh[r][c4 + u] = hb;
                Bl[r][c4 + u] = __float2bfloat16_rn(fb - __bfloat162float(hb));
            }
        }
        __syncthreads();

        #pragma unroll
        for (int kk = 0; kk < BK; kk += 16) {
            wmma::fragment<wmma::matrix_a, 16, 16, 16, __nv_bfloat16, wmma::row_major> ah[2], al[2];
            wmma::fragment<wmma::matrix_b, 16, 16, 16, __nv_bfloat16, wmma::col_major> bh[4], bl[4];
            #pragma unroll
            for (int i = 0; i < 2; i++) {
                wmma::load_matrix_sync(ah[i], &Ah[wr*32 + i*16][kk], ASTR);
                wmma::load_matrix_sync(al[i], &Al[wr*32 + i*16][kk], ASTR);
            }
            #pragma unroll
            for (int j = 0; j < 4; j++) {
                wmma::load_matrix_sync(bh[j], &Bh[wc*64 + j*16][kk], ASTR);
                wmma::load_matrix_sync(bl[j], &Bl[wc*64 + j*16][kk], ASTR);
            }
            #pragma unroll
            for (int i = 0; i < 2; i++)
                #pragma unroll
                for (int j = 0; j < 4; j++) {
                    wmma::mma_sync(acc[i][j], ah[i], bh[j], acc[i][j]);
                    wmma::mma_sync(acc[i][j], ah[i], bl[j], acc[i][j]);
                    wmma::mma_sync(acc[i][j], al[i], bh[j], acc[i][j]);
                }
        }
        __syncthreads();
    }

    #pragma unroll
    for (int i = 0; i < 2; i++)
        #pragma unroll
        for (int j = 0; j < 4; j++) {
            float* cp = &C[(size_t)(row0 + wr*32 + i*16) * N + col0 + wc*64 + j*16];
            wmma::store_matrix_sync(cp, acc[i][j], N, wmma::mem_row_major);
        }
}

// ---------------------------------------------------------------------------
// out[m, n] += bias[n]   (vectorized)
// ---------------------------------------------------------------------------
__global__ void bias_add_kernel(float* __restrict__ out,
                                const float* __restrict__ bias, int N4) {
    int idx = blockIdx.x * blockDim.x + threadIdx.x;
    float4 v = reinterpret_cast<float4*>(out)[idx];
    float4 b = reinterpret_cast<const float4*>(bias)[idx & (N4 - 1)];
    v.x += b.x; v.y += b.y; v.z += b.z; v.w += b.w;
    reinterpret_cast<float4*>(out)[idx] = v;
}

// ---------------------------------------------------------------------------
// Flash-attention style causal MHA, fp32. QKV bias folded into tile loads.
// ---------------------------------------------------------------------------
struct AttnSmem {
    float Qs[64][65];
    float Ks[64][65];
    float Vs[64][65];
    float Ps[64][65];
    float m_s[64];
    float l_s[64];
    float redm[64][16];
    float reds[64][16];
};

__global__ void attn_kernel(const float* __restrict__ qkv,
                            const float* __restrict__ b_qkv,
                            float* __restrict__ outp) {
    extern __shared__ char smem_raw[];
    AttnSmem& sm = *reinterpret_cast<AttnSmem*>(smem_raw);

    const int qt = blockIdx.x;   // 0..31
    const int h  = blockIdx.y;   // 0..15
    const int b  = blockIdx.z;   // 0..1
    const int tid = threadIdx.x;
    const int tx = tid & 15;
    const int ty = tid >> 4;
    const int q0 = qt * 64;

    // Load Q tile [64 x 64] (+ bias)
    for (int t = tid; t < 64*64; t += 256) {
        int r = t >> 6, d = t & 63;
        sm.Qs[r][d] = qkv[(size_t)(b*SS + q0 + r) * (3*DD) + h*HD + d] + b_qkv[h*HD + d];
    }
    if (tid < 64) { sm.m_s[tid] = -1e30f; sm.l_s[tid] = 0.0f; }

    float acc[4][4] = {};

    for (int kt = 0; kt <= qt; kt++) {
        const int k0 = kt * 64;
        __syncthreads();

        // Load K and V tiles (+ bias)
        for (int t = tid; t < 64*64; t += 256) {
            int r = t >> 6, d = t & 63;
            size_t base = (size_t)(b*SS + k0 + r) * (3*DD) + h*HD + d;
            sm.Ks[r][d] = qkv[base + DD]   + b_qkv[DD + h*HD + d];
            sm.Vs[r][d] = qkv[base + 2*DD] + b_qkv[2*DD + h*HD + d];
        }
        __syncthreads();

        // S = Q K^T
        float s[4][4] = {};
        #pragma unroll 8
        for (int d = 0; d < 64; d++) {
            float a[4], kf[4];
            #pragma unroll
            for (int i = 0; i < 4; i++) a[i] = sm.Qs[ty*4 + i][d];
            #pragma unroll
            for (int j = 0; j < 4; j++) kf[j] = sm.Ks[tx*4 + j][d];
            #pragma unroll
            for (int i = 0; i < 4; i++)
                #pragma unroll
                for (int j = 0; j < 4; j++)
                    s[i][j] += a[i] * kf[j];
        }

        // scale + causal mask + local row max
        #pragma unroll
        for (int i = 0; i < 4; i++) {
            int qg = q0 + ty*4 + i;
            float lm = -1e30f;
            #pragma unroll
            for (int j = 0; j < 4; j++) {
                int kg = k0 + tx*4 + j;
                float v = (kg <= qg) ? s[i][j] * 0.125f : -1e30f;
                s[i][j] = v;
                lm = fmaxf(lm, v);
            }
            sm.redm[ty*4 + i][tx] = lm;
        }
        __syncthreads();

        // online softmax update
        float scale_i[4], newm[4];
        #pragma unroll
        for (int i = 0; i < 4; i++) {
            int row = ty*4 + i;
            float tm = -1e30f;
            #pragma unroll
            for (int t2 = 0; t2 < 16; t2++) tm = fmaxf(tm, sm.redm[row][t2]);
            float om = sm.m_s[row];
            float nm = fmaxf(om, tm);
            newm[i] = nm;
            scale_i[i] = __expf(om - nm);
            float ls = 0.0f;
            #pragma unroll
            for (int j = 0; j < 4; j++) {
                float p = __expf(s[i][j] - nm);
                sm.Ps[row][tx*4 + j] = p;
                ls += p;
            }
            sm.reds[row][tx] = ls;
            #pragma unroll
            for (int j = 0; j < 4; j++) acc[i][j] *= scale_i[i];
        }
        __syncthreads();

        if (tx == 0) {
            #pragma unroll
            for (int i = 0; i < 4; i++) {
                int row = ty*4 + i;
                float tot = 0.0f;
                #pragma unroll
                for (int t2 = 0; t2 < 16; t2++) tot += sm.reds[row][t2];
                sm.l_s[row] = sm.l_s[row] * scale_i[i] + tot;
                sm.m_s[row] = newm[i];
            }
        }

        // O += P @ V
        #pragma unroll 8
        for (int c = 0; c < 64; c++) {
            float p[4], v[4];
            #pragma unroll
            for (int i = 0; i < 4; i++) p[i] = sm.Ps[ty*4 + i][c];
            #pragma unroll
            for (int j = 0; j < 4; j++) v[j] = sm.Vs[c][tx*4 + j];
            #pragma unroll
            for (int i = 0; i < 4; i++)
                #pragma unroll
                for (int j = 0; j < 4; j++)
                    acc[i][j] += p[i] * v[j];
        }
    }
    __syncthreads();

    // normalize and store to [B, S, H*Hd]
    #pragma unroll
    for (int i = 0; i < 4; i++) {
        int row = ty*4 + i;
        float inv = 1.0f / sm.l_s[row];
        #pragma unroll
        for (int j = 0; j < 4; j++) {
            outp[(size_t)(b*SS + q0 + row) * DD + h*HD + tx*4 + j] = acc[i][j] * inv;
        }
    }
}

// ---------------------------------------------------------------------------
extern "C" void kernel_launch(void* const* d_in, const int* in_sizes, int n_in,
                              void* d_out, int out_size) {
    const float* x     = (const float*)d_in[0];
    const float* W_qkv = (const float*)d_in[1];
    const float* b_qkv = (const float*)d_in[2];
    const float* W_out = (const float*)d_in[3];
    const float* b_out = (const float*)d_in[4];
    float* out = (float*)d_out;

    float *qkv_ptr = nullptr, *attn_ptr = nullptr;
    cudaGetSymbolAddress((void**)&qkv_ptr, g_qkv);
    cudaGetSymbolAddress((void**)&attn_ptr, g_attn);

    cudaFuncSetAttribute(attn_kernel,
                         cudaFuncAttributeMaxDynamicSharedMemorySize,
                         (int)sizeof(AttnSmem));

    // 1) QKV projection (no bias; folded into attention): [4096,3072]
    gemm_bf16x3_kernel<<<dim3(3*DD/128, MTOK/128), 256>>>(x, W_qkv, qkv_ptr,
                                                          MTOK, 3*DD, DD);

    // 2) causal attention (adds b_qkv on tile loads) -> [B*S, D]
    attn_kernel<<<dim3(SS/64, HH, BB), 256, sizeof(AttnSmem)>>>(qkv_ptr, b_qkv, attn_ptr);

    // 3) output projection: [4096,1024]
    gemm_bf16x3_kernel<<<dim3(DD/128, MTOK/128), 256>>>(attn_ptr, W_out, out,
                                                        MTOK, DD, DD);

    // 4) + b_out
    bias_add_kernel<<<(MTOK*DD/4)/256, 256>>>(out, b_out, DD/4);
}

// round 4
// speedup vs baseline: 1.8928x; 1.2137x over previous
#include <cuda_runtime.h>
#include <cuda_bf16.h>
#include <mma.h>
#include <math.h>

using namespace nvcuda;

#define BB 2
#define SS 2048
#define DD 1024
#define HH 16
#define HD 64
#define MTOK (BB*SS)   // 4096

// Scratch (allocation-free rule: __device__ globals)
__device__ float g_qkv[BB*SS*3*DD];   // [B*S, 3D]  (NO bias; folded into attention)
__device__ float g_attn[BB*SS*DD];    // [B*S, D]

// ---------------------------------------------------------------------------
// C[M,N] = A[M,K] @ W[N,K]^T   via 3-term bf16-split tensor-core MMA.
// ---------------------------------------------------------------------------
#define BK 32
#define ASTR 40   // smem row stride (bf16 elems)

__global__ __launch_bounds__(256)
void gemm_bf16x3_kernel(const float* __restrict__ A,
                        const float* __restrict__ W,
                        float* __restrict__ C,
                        int M, int N, int K) {
    __shared__ __nv_bfloat16 Ah[128][ASTR];
    __shared__ __nv_bfloat16 Al[128][ASTR];
    __shared__ __nv_bfloat16 Bh[128][ASTR];
    __shared__ __nv_bfloat16 Bl[128][ASTR];

    const int tid = threadIdx.x;
    const int warp = tid >> 5;
    const int wr = warp >> 1;
    const int wc = warp & 1;
    const int row0 = blockIdx.y * 128;
    const int col0 = blockIdx.x * 128;

    wmma::fragment<wmma::accumulator, 16, 16, 16, float> acc[2][4];
    #pragma unroll
    for (int i = 0; i < 2; i++)
        #pragma unroll
        for (int j = 0; j < 4; j++)
            wmma::fill_fragment(acc[i][j], 0.0f);

    for (int k0 = 0; k0 < K; k0 += BK) {
        #pragma unroll
        for (int t = tid; t < 1024; t += 256) {
            int r = t >> 3, c4 = (t & 7) * 4;
            float4 va = *reinterpret_cast<const float4*>(&A[(size_t)(row0 + r) * K + k0 + c4]);
            float4 vb = *reinterpret_cast<const float4*>(&W[(size_t)(col0 + r) * K + k0 + c4]);
            #pragma unroll
            for (int u = 0; u < 4; u++) {
                float fa = (&va.x)[u];
                __nv_bfloat16 ha = __float2bfloat16_rn(fa);
                Ah[r][c4 + u] = ha;
                Al[r][c4 + u] = __float2bfloat16_rn(fa - __bfloat162float(ha));
                float fb = (&vb.x)[u];
                __nv_bfloat16 hb = __float2bfloat16_rn(fb);
                Bh[r][c4 + u] = hb;
                Bl[r][c4 + u] = __float2bfloat16_rn(fb - __bfloat162float(hb));
            }
        }
        __syncthreads();

        #pragma unroll
        for (int kk = 0; kk < BK; kk += 16) {
            wmma::fragment<wmma::matrix_a, 16, 16, 16, __nv_bfloat16, wmma::row_major> ah[2], al[2];
            wmma::fragment<wmma::matrix_b, 16, 16, 16, __nv_bfloat16, wmma::col_major> bh[4], bl[4];
            #pragma unroll
            for (int i = 0; i < 2; i++) {
                wmma::load_matrix_sync(ah[i], &Ah[wr*32 + i*16][kk], ASTR);
                wmma::load_matrix_sync(al[i], &Al[wr*32 + i*16][kk], ASTR);
            }
            #pragma unroll
            for (int j = 0; j < 4; j++) {
                wmma::load_matrix_sync(bh[j], &Bh[wc*64 + j*16][kk], ASTR);
                wmma::load_matrix_sync(bl[j], &Bl[wc*64 + j*16][kk], ASTR);
            }
            #pragma unroll
            for (int i = 0; i < 2; i++)
                #pragma unroll
                for (int j = 0; j < 4; j++) {
                    wmma::mma_sync(acc[i][j], ah[i], bh[j], acc[i][j]);
                    wmma::mma_sync(acc[i][j], ah[i], bl[j], acc[i][j]);
                    wmma::mma_sync(acc[i][j], al[i], bh[j], acc[i][j]);
                }
        }
        __syncthreads();
    }

    #pragma unroll
    for (int i = 0; i < 2; i++)
        #pragma unroll
        for (int j = 0; j < 4; j++) {
            float* cp = &C[(size_t)(row0 + wr*32 + i*16) * N + col0 + wc*64 + j*16];
            wmma::store_matrix_sync(cp, acc[i][j], N, wmma::mem_row_major);
        }
}

// ---------------------------------------------------------------------------
__global__ void bias_add_kernel(float* __restrict__ out,
                                const float* __restrict__ bias, int N4) {
    int idx = blockIdx.x * blockDim.x + threadIdx.x;
    float4 v = reinterpret_cast<float4*>(out)[idx];
    float4 b = reinterpret_cast<const float4*>(bias)[idx & (N4 - 1)];
    v.x += b.x; v.y += b.y; v.z += b.z; v.w += b.w;
    reinterpret_cast<float4*>(out)[idx] = v;
}

// ---------------------------------------------------------------------------
// Tensor-core flash attention (bf16x3 QK^T and PV, fp32 softmax/state).
// CTA = (q-tile 64, head, batch). 8 warps. O accumulator in smem fp32.
// ---------------------------------------------------------------------------
#define SB 72   // bf16 smem stride
#define SF 68   // fp32 smem stride

struct AttnSmem {
    __nv_bfloat16 Qh[64][SB], Ql[64][SB];
    __nv_bfloat16 Kh[64][SB], Kl[64][SB];
    __nv_bfloat16 Vh[64][SB], Vl[64][SB];
    __nv_bfloat16 Ph[64][SB], Pl[64][SB];
    float S[64][SF];         // S tile; reused as PV staging buffer
    float O[64][SF];
    float m_s[64], l_s[64], resc[64];
};

__global__ __launch_bounds__(256)
void attn_wmma_kernel(const float* __restrict__ qkv,
                      const float* __restrict__ b_qkv,
                      float* __restrict__ outp) {
    extern __shared__ char smem_raw[];
    AttnSmem& sm = *reinterpret_cast<AttnSmem*>(smem_raw);

    const int qt = blockIdx.x;
    const int h  = blockIdx.y;
    const int b  = blockIdx.z;
    const int tid = threadIdx.x;
    const int warp = tid >> 5;
    const int wr = warp >> 2;          // 0..1 : 32-row slab
    const int wc = warp & 3;           // 0..3 : 16-col slab
    const int q0 = qt * 64;

    // Load Q (+bias), split hi/lo; init O/m/l
    for (int t = tid; t < 64*64; t += 256) {
        int r = t >> 6, d = t & 63;
        float v = qkv[(size_t)(b*SS + q0 + r) * (3*DD) + h*HD + d] + b_qkv[h*HD + d];
        __nv_bfloat16 hi = __float2bfloat16_rn(v);
        sm.Qh[r][d] = hi;
        sm.Ql[r][d] = __float2bfloat16_rn(v - __bfloat162float(hi));
        sm.O[r][d] = 0.0f;
    }
    if (tid < 64) { sm.m_s[tid] = -1e30f; sm.l_s[tid] = 0.0f; }
    __syncthreads();

    const int srow = tid >> 2;          // softmax row (0..63)
    const int sq   = tid & 3;           // quarter (16 cols)
    const int cb   = sq * 16;

    for (int kt = 0; kt <= qt; kt++) {
        const int k0 = kt * 64;

        // Load K/V (+bias), split hi/lo
        for (int t = tid; t < 64*64; t += 256) {
            int r = t >> 6, d = t & 63;
            size_t base = (size_t)(b*SS + k0 + r) * (3*DD) + h*HD + d;
            float kv = qkv[base + DD] + b_qkv[DD + h*HD + d];
            __nv_bfloat16 kh = __float2bfloat16_rn(kv);
            sm.Kh[r][d] = kh;
            sm.Kl[r][d] = __float2bfloat16_rn(kv - __bfloat162float(kh));
            float vv = qkv[base + 2*DD] + b_qkv[2*DD + h*HD + d];
            __nv_bfloat16 vh = __float2bfloat16_rn(vv);
            sm.Vh[r][d] = vh;
            sm.Vl[r][d] = __float2bfloat16_rn(vv - __bfloat162float(vh));
        }
        __syncthreads();

        // ---- S = Q @ K^T (bf16x3) ----
        {
            wmma::fragment<wmma::accumulator, 16, 16, 16, float> sacc[2];
            wmma::fill_fragment(sacc[0], 0.0f);
            wmma::fill_fragment(sacc[1], 0.0f);
            #pragma unroll
            for (int ks = 0; ks < 4; ks++) {
                int kk = ks * 16;
                wmma::fragment<wmma::matrix_a, 16, 16, 16, __nv_bfloat16, wmma::row_major> ah[2], al[2];
                wmma::fragment<wmma::matrix_b, 16, 16, 16, __nv_bfloat16, wmma::col_major> bh, bl;
                #pragma unroll
                for (int i = 0; i < 2; i++) {
                    wmma::load_matrix_sync(ah[i], &sm.Qh[wr*32 + i*16][kk], SB);
                    wmma::load_matrix_sync(al[i], &sm.Ql[wr*32 + i*16][kk], SB);
                }
                wmma::load_matrix_sync(bh, &sm.Kh[wc*16][kk], SB);
                wmma::load_matrix_sync(bl, &sm.Kl[wc*16][kk], SB);
                #pragma unroll
                for (int i = 0; i < 2; i++) {
                    wmma::mma_sync(sacc[i], ah[i], bh, sacc[i]);
                    wmma::mma_sync(sacc[i], ah[i], bl, sacc[i]);
                    wmma::mma_sync(sacc[i], al[i], bh, sacc[i]);
                }
            }
            #pragma unroll
            for (int i = 0; i < 2; i++)
                wmma::store_matrix_sync(&sm.S[wr*32 + i*16][wc*16], sacc[i], SF, wmma::mem_row_major);
        }
        __syncthreads();

        // ---- online softmax (4 threads per row) ----
        {
            const bool diag = (kt == qt);
            float sv[16];
            float mloc = -1e30f;
            #pragma unroll
            for (int c = 0; c < 16; c++) {
                float s = sm.S[srow][cb + c] * 0.125f;
                if (diag && (k0 + cb + c > q0 + srow)) s = -1e30f;
                sv[c] = s;
                mloc = fmaxf(mloc, s);
            }
            mloc = fmaxf(mloc, __shfl_xor_sync(0xFFFFFFFF, mloc, 1));
            mloc = fmaxf(mloc, __shfl_xor_sync(0xFFFFFFFF, mloc, 2));
            float mold = sm.m_s[srow];
            float nm = fmaxf(mold, mloc);
            float ls = 0.0f;
            #pragma unroll
            for (int c = 0; c < 16; c++) {
                float p = __expf(sv[c] - nm);
                ls += p;
                __nv_bfloat16 ph = __float2bfloat16_rn(p);
                sm.Ph[srow][cb + c] = ph;
                sm.Pl[srow][cb + c] = __float2bfloat16_rn(p - __bfloat162float(ph));
            }
            ls += __shfl_xor_sync(0xFFFFFFFF, ls, 1);
            ls += __shfl_xor_sync(0xFFFFFFFF, ls, 2);
            if (sq == 0) {
                float rs = __expf(mold - nm);
                sm.resc[srow] = rs;
                sm.l_s[srow] = sm.l_s[srow] * rs + ls;
                sm.m_s[srow] = nm;
            }
        }
        __syncthreads();

        // ---- PV = P @ V (bf16x3) -> stage into S buffer ----
        {
            wmma::fragment<wmma::accumulator, 16, 16, 16, float> pacc[2];
            wmma::fill_fragment(pacc[0], 0.0f);
            wmma::fill_fragment(pacc[1], 0.0f);
            #pragma unroll
            for (int ks = 0; ks < 4; ks++) {
                int kk = ks * 16;
                wmma::fragment<wmma::matrix_a, 16, 16, 16, __nv_bfloat16, wmma::row_major> ah[2], al[2];
                wmma::fragment<wmma::matrix_b, 16, 16, 16, __nv_bfloat16, wmma::row_major> bh, bl;
                #pragma unroll
                for (int i = 0; i < 2; i++) {
                    wmma::load_matrix_sync(ah[i], &sm.Ph[wr*32 + i*16][kk], SB);
                    wmma::load_matrix_sync(al[i], &sm.Pl[wr*32 + i*16][kk], SB);
                }
                wmma::load_matrix_sync(bh, &sm.Vh[kk][wc*16], SB);
                wmma::load_matrix_sync(bl, &sm.Vl[kk][wc*16], SB);
                #pragma unroll
                for (int i = 0; i < 2; i++) {
                    wmma::mma_sync(pacc[i], ah[i], bh, pacc[i]);
                    wmma::mma_sync(pacc[i], ah[i], bl, pacc[i]);
                    wmma::mma_sync(pacc[i], al[i], bh, pacc[i]);
                }
            }
            #pragma unroll
            for (int i = 0; i < 2; i++)
                wmma::store_matrix_sync(&sm.S[wr*32 + i*16][wc*16], pacc[i], SF, wmma::mem_row_major);
        }
        __syncthreads();

        // ---- O = O * resc + PV ----
        {
            float rs = sm.resc[srow];
            #pragma unroll
            for (int c = 0; c < 16; c++)
                sm.O[srow][cb + c] = sm.O[srow][cb + c] * rs + sm.S[srow][cb + c];
        }
        __syncthreads();
    }

    // normalize and write [B, S, H*Hd]
    {
        float inv = 1.0f / sm.l_s[srow];
        #pragma unroll
        for (int c = 0; c < 16; c++)
            outp[(size_t)(b*SS + q0 + srow) * DD + h*HD + cb + c] = sm.O[srow][cb + c] * inv;
    }
}

// ---------------------------------------------------------------------------
extern "C" void kernel_launch(void* const* d_in, const int* in_sizes, int n_in,
                              void* d_out, int out_size) {
    const float* x     = (const float*)d_in[0];
    const float* W_qkv = (const float*)d_in[1];
    const float* b_qkv = (const float*)d_in[2];
    const float* W_out = (const float*)d_in[3];
    const float* b_out = (const float*)d_in[4];
    float* out = (float*)d_out;

    float *qkv_ptr = nullptr, *attn_ptr = nullptr;
    cudaGetSymbolAddress((void**)&qkv_ptr, g_qkv);
    cudaGetSymbolAddress((void**)&attn_ptr, g_attn);

    cudaFuncSetAttribute(attn_wmma_kernel,
                         cudaFuncAttributeMaxDynamicSharedMemorySize,
                         (int)sizeof(AttnSmem));

    // 1) QKV projection (bias folded into attention): [4096,3072]
    gemm_bf16x3_kernel<<<dim3(3*DD/128, MTOK/128), 256>>>(x, W_qkv, qkv_ptr,
                                                          MTOK, 3*DD, DD);

    // 2) tensor-core causal attention -> [B*S, D]
    attn_wmma_kernel<<<dim3(SS/64, HH, BB), 256, sizeof(AttnSmem)>>>(qkv_ptr, b_qkv, attn_ptr);

    // 3) output projection: [4096,1024]
    gemm_bf16x3_kernel<<<dim3(DD/128, MTOK/128), 256>>>(attn_ptr, W_out, out,
                                                        MTOK, DD, DD);

    // 4) + b_out
    bias_add_kernel<<<(MTOK*DD/4)/256, 256>>>(out, b_out, DD/4);
}

// round 5
// speedup vs baseline: 1.9629x; 1.0370x over previous
#include <cuda_runtime.h>
#include <cuda_bf16.h>
#include <mma.h>
#include <math.h>

using namespace nvcuda;

#define BB 2
#define SS 2048
#define DD 1024
#define HH 16
#define HD 64
#define MTOK (BB*SS)   // 4096

// Scratch (allocation-free rule: __device__ globals)
__device__ float g_qkv[BB*SS*3*DD];              // fp32 qkv (no bias)
__device__ __nv_bfloat16 g_qkv_hi[BB*SS*3*DD];   // bf16 hi of (qkv + bias)
__device__ __nv_bfloat16 g_qkv_lo[BB*SS*3*DD];   // bf16 lo
__device__ float g_attn[BB*SS*DD];

// ---------------------------------------------------------------------------
// C[M,N] = A[M,K] @ W[N,K]^T   via 3-term bf16-split tensor-core MMA.
// ---------------------------------------------------------------------------
#define BK 32
#define ASTR 40

__global__ __launch_bounds__(256)
void gemm_bf16x3_kernel(const float* __restrict__ A,
                        const float* __restrict__ W,
                        float* __restrict__ C,
                        int M, int N, int K) {
    __shared__ __nv_bfloat16 Ah[128][ASTR];
    __shared__ __nv_bfloat16 Al[128][ASTR];
    __shared__ __nv_bfloat16 Bh[128][ASTR];
    __shared__ __nv_bfloat16 Bl[128][ASTR];

    const int tid = threadIdx.x;
    const int warp = tid >> 5;
    const int wr = warp >> 1;
    const int wc = warp & 1;
    const int row0 = blockIdx.y * 128;
    const int col0 = blockIdx.x * 128;

    wmma::fragment<wmma::accumulator, 16, 16, 16, float> acc[2][4];
    #pragma unroll
    for (int i = 0; i < 2; i++)
        #pragma unroll
        for (int j = 0; j < 4; j++)
            wmma::fill_fragment(acc[i][j], 0.0f);

    for (int k0 = 0; k0 < K; k0 += BK) {
        #pragma unroll
        for (int t = tid; t < 1024; t += 256) {
            int r = t >> 3, c4 = (t & 7) * 4;
            float4 va = *reinterpret_cast<const float4*>(&A[(size_t)(row0 + r) * K + k0 + c4]);
            float4 vb = *reinterpret_cast<const float4*>(&W[(size_t)(col0 + r) * K + k0 + c4]);
            #pragma unroll
            for (int u = 0; u < 4; u++) {
                float fa = (&va.x)[u];
                __nv_bfloat16 ha = __float2bfloat16_rn(fa);
                Ah[r][c4 + u] = ha;
                Al[r][c4 + u] = __float2bfloat16_rn(fa - __bfloat162float(ha));
                float fb = (&vb.x)[u];
                __nv_bfloat16 hb = __float2bfloat16_rn(fb);
                Bh[r][c4 + u] = hb;
                Bl[r][c4 + u] = __float2bfloat16_rn(fb - __bfloat162float(hb));
            }
        }
        __syncthreads();

        #pragma unroll
        for (int kk = 0; kk < BK; kk += 16) {
            wmma::fragment<wmma::matrix_a, 16, 16, 16, __nv_bfloat16, wmma::row_major> ah[2], al[2];
            wmma::fragment<wmma::matrix_b, 16, 16, 16, __nv_bfloat16, wmma::col_major> bh[4], bl[4];
            #pragma unroll
            for (int i = 0; i < 2; i++) {
                wmma::load_matrix_sync(ah[i], &Ah[wr*32 + i*16][kk], ASTR);
                wmma::load_matrix_sync(al[i], &Al[wr*32 + i*16][kk], ASTR);
            }
            #pragma unroll
            for (int j = 0; j < 4; j++) {
                wmma::load_matrix_sync(bh[j], &Bh[wc*64 + j*16][kk], ASTR);
                wmma::load_matrix_sync(bl[j], &Bl[wc*64 + j*16][kk], ASTR);
            }
            #pragma unroll
            for (int i = 0; i < 2; i++)
                #pragma unroll
                for (int j = 0; j < 4; j++) {
                    wmma::mma_sync(acc[i][j], ah[i], bh[j], acc[i][j]);
                    wmma::mma_sync(acc[i][j], ah[i], bl[j], acc[i][j]);
                    wmma::mma_sync(acc[i][j], al[i], bh[j], acc[i][j]);
                }
        }
        __syncthreads();
    }

    #pragma unroll
    for (int i = 0; i < 2; i++)
        #pragma unroll
        for (int j = 0; j < 4; j++) {
            float* cp = &C[(size_t)(row0 + wr*32 + i*16) * N + col0 + wc*64 + j*16];
            wmma::store_matrix_sync(cp, acc[i][j], N, wmma::mem_row_major);
        }
}

// ---------------------------------------------------------------------------
// qkv fp32 + bias -> hi/lo bf16 split (one float4 per thread)
// ---------------------------------------------------------------------------
__global__ void split_kernel(const float* __restrict__ in,
                             const float* __restrict__ bias,
                             __nv_bfloat16* __restrict__ hi,
                             __nv_bfloat16* __restrict__ lo,
                             int rowlen4) {
    int idx = blockIdx.x * blockDim.x + threadIdx.x;
    float4 v = reinterpret_cast<const float4*>(in)[idx];
    float4 bv = reinterpret_cast<const float4*>(bias)[idx % rowlen4];
    __nv_bfloat162 h2[2], l2[2];
    #pragma unroll
    for (int u = 0; u < 4; u++) {
        float f = (&v.x)[u] + (&bv.x)[u];
        __nv_bfloat16 h = __float2bfloat16_rn(f);
        __nv_bfloat16 l = __float2bfloat16_rn(f - __bfloat162float(h));
        ((__nv_bfloat16*)h2)[u] = h;
        ((__nv_bfloat16*)l2)[u] = l;
    }
    reinterpret_cast<__nv_bfloat162*>(hi)[idx*2]   = h2[0];
    reinterpret_cast<__nv_bfloat162*>(hi)[idx*2+1] = h2[1];
    reinterpret_cast<__nv_bfloat162*>(lo)[idx*2]   = l2[0];
    reinterpret_cast<__nv_bfloat162*>(lo)[idx*2+1] = l2[1];
}

// ---------------------------------------------------------------------------
__global__ void bias_add_kernel(float* __restrict__ out,
                                const float* __restrict__ bias, int N4) {
    int idx = blockIdx.x * blockDim.x + threadIdx.x;
    float4 v = reinterpret_cast<float4*>(out)[idx];
    float4 b = reinterpret_cast<const float4*>(bias)[idx & (N4 - 1)];
    v.x += b.x; v.y += b.y; v.z += b.z; v.w += b.w;
    reinterpret_cast<float4*>(out)[idx] = v;
}

// ---------------------------------------------------------------------------
// Tensor-core flash attention. Q-tile 128, kv-tile 64, 512 threads (16 warps).
// Inputs pre-split bf16 hi/lo (bias already applied). fp32 softmax state.
// Warp tile: 16 rows x 32 cols (wr=warp>>1 in 0..7, wc=warp&1).
// ---------------------------------------------------------------------------
#define SB 72   // bf16 smem stride
#define SF 68   // fp32 smem stride

struct AttnSmem {
    __nv_bfloat16 Qh[128][SB], Ql[128][SB];
    __nv_bfloat16 Kh[64][SB],  Kl[64][SB];
    __nv_bfloat16 Vh[64][SB],  Vl[64][SB];
    __nv_bfloat16 Ph[128][SB], Pl[128][SB];
    float S[128][SF];          // S staging; reused as PV staging
    float O[128][SF];
    float m_s[128], l_s[128], resc[128];
};

__global__ __launch_bounds__(512)
void attn_wmma_kernel(const __nv_bfloat16* __restrict__ qhi,
                      const __nv_bfloat16* __restrict__ qlo,
                      float* __restrict__ outp) {
    extern __shared__ char smem_raw[];
    AttnSmem& sm = *reinterpret_cast<AttnSmem*>(smem_raw);

    const int qt = gridDim.x - 1 - blockIdx.x;   // longest first
    const int h  = blockIdx.y;
    const int b  = blockIdx.z;
    const int tid = threadIdx.x;
    const int warp = tid >> 5;
    const int lane = tid & 31;
    const int wr = warp >> 1;        // 0..7 : 16-row slab
    const int wc = warp & 1;         // 0..1 : 32-col slab
    const int q0 = qt * 128;

    // Load Q hi/lo (uint4 = 8 bf16), zero O
    for (int t = tid; t < 128*8; t += 512) {
        int r = t >> 3, c8 = (t & 7) * 8;
        size_t g = (size_t)(b*SS + q0 + r) * (3*DD) + h*HD + c8;
        *reinterpret_cast<uint4*>(&sm.Qh[r][c8]) = *reinterpret_cast<const uint4*>(&qhi[g]);
        *reinterpret_cast<uint4*>(&sm.Ql[r][c8]) = *reinterpret_cast<const uint4*>(&qlo[g]);
    }
    for (int t = tid; t < 128*16; t += 512) {
        int r = t >> 4, c4 = (t & 15) * 4;
        *reinterpret_cast<float4*>(&sm.O[r][c4]) = make_float4(0.f, 0.f, 0.f, 0.f);
    }
    if (tid < 128) { sm.m_s[tid] = -1e30f; sm.l_s[tid] = 0.0f; }
    __syncthreads();

    const int srow = tid >> 2;        // 0..127
    const int sq   = tid & 3;
    const int cb   = sq * 16;
    const int nkt  = 2*qt + 2;

    for (int kt = 0; kt < nkt; kt++) {
        const int k0 = kt * 64;

        // Load K/V hi/lo tiles (pure copies)
        for (int t = tid; t < 64*8; t += 512) {
            int r = t >> 3, c8 = (t & 7) * 8;
            size_t base = (size_t)(b*SS + k0 + r) * (3*DD) + h*HD + c8;
            *reinterpret_cast<uint4*>(&sm.Kh[r][c8]) = *reinterpret_cast<const uint4*>(&qhi[base + DD]);
            *reinterpret_cast<uint4*>(&sm.Kl[r][c8]) = *reinterpret_cast<const uint4*>(&qlo[base + DD]);
            *reinterpret_cast<uint4*>(&sm.Vh[r][c8]) = *reinterpret_cast<const uint4*>(&qhi[base + 2*DD]);
            *reinterpret_cast<uint4*>(&sm.Vl[r][c8]) = *reinterpret_cast<const uint4*>(&qlo[base + 2*DD]);
        }
        __syncthreads();

        // ---- S = Q @ K^T (bf16x3): warp -> rows [16wr,+16) cols [32wc,+32)
        {
            wmma::fragment<wmma::accumulator, 16, 16, 16, float> s0, s1;
            wmma::fill_fragment(s0, 0.0f);
            wmma::fill_fragment(s1, 0.0f);
            #pragma unroll
            for (int ks = 0; ks < 4; ks++) {
                int kk = ks * 16;
                wmma::fragment<wmma::matrix_a, 16, 16, 16, __nv_bfloat16, wmma::row_major> ah, al;
                wmma::fragment<wmma::matrix_b, 16, 16, 16, __nv_bfloat16, wmma::col_major> bh0, bh1, bl0, bl1;
                wmma::load_matrix_sync(ah, &sm.Qh[wr*16][kk], SB);
                wmma::load_matrix_sync(al, &sm.Ql[wr*16][kk], SB);
                wmma::load_matrix_sync(bh0, &sm.Kh[wc*32][kk], SB);
                wmma::load_matrix_sync(bh1, &sm.Kh[wc*32+16][kk], SB);
                wmma::load_matrix_sync(bl0, &sm.Kl[wc*32][kk], SB);
                wmma::load_matrix_sync(bl1, &sm.Kl[wc*32+16][kk], SB);
                wmma::mma_sync(s0, ah, bh0, s0);
                wmma::mma_sync(s0, ah, bl0, s0);
                wmma::mma_sync(s0, al, bh0, s0);
                wmma::mma_sync(s1, ah, bh1, s1);
                wmma::mma_sync(s1, ah, bl1, s1);
                wmma::mma_sync(s1, al, bh1, s1);
            }
            wmma::store_matrix_sync(&sm.S[wr*16][wc*32],      s0, SF, wmma::mem_row_major);
            wmma::store_matrix_sync(&sm.S[wr*16][wc*32 + 16], s1, SF, wmma::mem_row_major);
        }
        __syncthreads();

        // ---- online softmax (4 threads per row, 16 cols each) ----
        {
            const bool diag = (kt >= 2*qt);
            float sv[16];
            float mloc = -1e30f;
            #pragma unroll
            for (int c = 0; c < 16; c++) {
                float s = sm.S[srow][cb + c] * 0.125f;
                if (diag && (k0 + cb + c > q0 + srow)) s = -1e30f;
                sv[c] = s;
                mloc = fmaxf(mloc, s);
            }
            mloc = fmaxf(mloc, __shfl_xor_sync(0xFFFFFFFF, mloc, 1));
            mloc = fmaxf(mloc, __shfl_xor_sync(0xFFFFFFFF, mloc, 2));
            float mold = sm.m_s[srow];
            float nm = fmaxf(mold, mloc);
            float ls = 0.0f;
            #pragma unroll
            for (int c = 0; c < 16; c++) {
                float p = __expf(sv[c] - nm);
                ls += p;
                __nv_bfloat16 ph = __float2bfloat16_rn(p);
                sm.Ph[srow][cb + c] = ph;
                sm.Pl[srow][cb + c] = __float2bfloat16_rn(p - __bfloat162float(ph));
            }
            ls += __shfl_xor_sync(0xFFFFFFFF, ls, 1);
            ls += __shfl_xor_sync(0xFFFFFFFF, ls, 2);
            if (sq == 0) {
                float rs = __expf(mold - nm);
                sm.resc[srow] = rs;
                sm.l_s[srow] = sm.l_s[srow] * rs + ls;
                sm.m_s[srow] = nm;
            }
        }
        __syncthreads();

        // ---- PV = P @ V (bf16x3), then warp-local O update ----
        {
            wmma::fragment<wmma::accumulator, 16, 16, 16, float> p0, p1;
            wmma::fill_fragment(p0, 0.0f);
            wmma::fill_fragment(p1, 0.0f);
            #pragma unroll
            for (int ks = 0; ks < 4; ks++) {
                int kk = ks * 16;
                wmma::fragment<wmma::matrix_a, 16, 16, 16, __nv_bfloat16, wmma::row_major> ah, al;
                wmma::fragment<wmma::matrix_b, 16, 16, 16, __nv_bfloat16, wmma::row_major> bh0, bh1, bl0, bl1;
                wmma::load_matrix_sync(ah, &sm.Ph[wr*16][kk], SB);
                wmma::load_matrix_sync(al, &sm.Pl[wr*16][kk], SB);
                wmma::load_matrix_sync(bh0, &sm.Vh[kk][wc*32], SB);
                wmma::load_matrix_sync(bh1, &sm.Vh[kk][wc*32+16], SB);
                wmma::load_matrix_sync(bl0, &sm.Vl[kk][wc*32], SB);
                wmma::load_matrix_sync(bl1, &sm.Vl[kk][wc*32+16], SB);
                wmma::mma_sync(p0, ah, bh0, p0);
                wmma::mma_sync(p0, ah, bl0, p0);
                wmma::mma_sync(p0, al, bh0, p0);
                wmma::mma_sync(p1, ah, bh1, p1);
                wmma::mma_sync(p1, ah, bl1, p1);
                wmma::mma_sync(p1, al, bh1, p1);
            }
            wmma::store_matrix_sync(&sm.S[wr*16][wc*32],      p0, SF, wmma::mem_row_major);
            wmma::store_matrix_sync(&sm.S[wr*16][wc*32 + 16], p1, SF, wmma::mem_row_major);
            __syncwarp();
            // O[r][c] = O[r][c]*resc[r] + PV[r][c] over this warp's region
            int r = wr*16 + (lane >> 1);
            int c0 = wc*32 + (lane & 1) * 16;
            float rs = sm.resc[r];
            #pragma unroll
            for (int c = 0; c < 16; c++)
                sm.O[r][c0 + c] = sm.O[r][c0 + c] * rs + sm.S[r][c0 + c];
        }
        __syncthreads();
    }

    // normalize and write [B, S, H*Hd]
    {
        float inv = 1.0f / sm.l_s[srow];
        #pragma unroll
        for (int c = 0; c < 16; c++)
            outp[(size_t)(b*SS + q0 + srow) * DD + h*HD + cb + c] = sm.O[srow][cb + c] * inv;
    }
}

// ---------------------------------------------------------------------------
extern "C" void kernel_launch(void* const* d_in, const int* in_sizes, int n_in,
                              void* d_out, int out_size) {
    const float* x     = (const float*)d_in[0];
    const float* W_qkv = (const float*)d_in[1];
    const float* b_qkv = (const float*)d_in[2];
    const float* W_out = (const float*)d_in[3];
    const float* b_out = (const float*)d_in[4];
    float* out = (float*)d_out;

    float *qkv_ptr = nullptr, *attn_ptr = nullptr;
    __nv_bfloat16 *qhi = nullptr, *qlo = nullptr;
    cudaGetSymbolAddress((void**)&qkv_ptr, g_qkv);
    cudaGetSymbolAddress((void**)&attn_ptr, g_attn);
    cudaGetSymbolAddress((void**)&qhi, g_qkv_hi);
    cudaGetSymbolAddress((void**)&qlo, g_qkv_lo);

    cudaFuncSetAttribute(attn_wmma_kernel,
                         cudaFuncAttributeMaxDynamicSharedMemorySize,
                         (int)sizeof(AttnSmem));

    // 1) QKV projection (no bias): [4096,3072]
    gemm_bf16x3_kernel<<<dim3(3*DD/128, MTOK/128), 256>>>(x, W_qkv, qkv_ptr,
                                                          MTOK, 3*DD, DD);

    // 2) split fp32 qkv + bias -> bf16 hi/lo
    split_kernel<<<(MTOK*3*DD/4)/256, 256>>>(qkv_ptr, b_qkv, qhi, qlo, 3*DD/4);

    // 3) tensor-core causal attention -> [B*S, D]
    attn_wmma_kernel<<<dim3(SS/128, HH, BB), 512, sizeof(AttnSmem)>>>(qhi, qlo, attn_ptr);

    // 4) output projection: [4096,1024]
    gemm_bf16x3_kernel<<<dim3(DD/128, MTOK/128), 256>>>(attn_ptr, W_out, out,
                                                        MTOK, DD, DD);

    // 5) + b_out
    bias_add_kernel<<<(MTOK*DD/4)/256, 256>>>(out, b_out, DD/4);
}

// round 8
// speedup vs baseline: 2.5313x; 1.2896x over previous
#include <cuda_runtime.h>
#include <cuda_bf16.h>
#include <cuda_pipeline.h>
#include <mma.h>
#include <math.h>

using namespace nvcuda;

#define BB 2
#define SS 2048
#define DD 1024
#define HH 16
#define HD 64
#define MTOK (BB*SS)

// Scratch (allocation-free rule: __device__ globals)
__device__ float g_qkv[BB*SS*3*DD];
__device__ __nv_bfloat16 g_qkv_hi[BB*SS*3*DD];
__device__ __nv_bfloat16 g_qkv_lo[BB*SS*3*DD];
__device__ __nv_bfloat16 g_xh[MTOK*DD];
__device__ __nv_bfloat16 g_xl[MTOK*DD];
__device__ __nv_bfloat16 g_wqh[3*DD*DD];
__device__ __nv_bfloat16 g_wql[3*DD*DD];
__device__ __nv_bfloat16 g_woh[DD*DD];
__device__ __nv_bfloat16 g_wol[DD*DD];
__device__ __nv_bfloat16 g_oh[MTOK*DD];
__device__ __nv_bfloat16 g_ol[MTOK*DD];

// ===========================================================================
// split kernels
// ===========================================================================
__global__ void split_nobias_kernel(const float* __restrict__ in,
                                    __nv_bfloat16* __restrict__ hi,
                                    __nv_bfloat16* __restrict__ lo) {
    int idx = blockIdx.x * blockDim.x + threadIdx.x;
    float4 v = reinterpret_cast<const float4*>(in)[idx];
    __nv_bfloat162 h2[2];
    __nv_bfloat162 l2[2];
    #pragma unroll
    for (int u = 0; u < 4; u++) {
        float f = (&v.x)[u];
        __nv_bfloat16 h = __float2bfloat16_rn(f);
        ((__nv_bfloat16*)h2)[u] = h;
        ((__nv_bfloat16*)l2)[u] = __float2bfloat16_rn(f - __bfloat162float(h));
    }
    reinterpret_cast<__nv_bfloat162*>(hi)[idx*2]   = h2[0];
    reinterpret_cast<__nv_bfloat162*>(hi)[idx*2+1] = h2[1];
    reinterpret_cast<__nv_bfloat162*>(lo)[idx*2]   = l2[0];
    reinterpret_cast<__nv_bfloat162*>(lo)[idx*2+1] = l2[1];
}

__global__ void split_bias_kernel(const float* __restrict__ in,
                                  const float* __restrict__ bias,
                                  __nv_bfloat16* __restrict__ hi,
                                  __nv_bfloat16* __restrict__ lo,
                                  int rowlen4) {
    int idx = blockIdx.x * blockDim.x + threadIdx.x;
    float4 v = reinterpret_cast<const float4*>(in)[idx];
    float4 bv = reinterpret_cast<const float4*>(bias)[idx % rowlen4];
    __nv_bfloat162 h2[2];
    __nv_bfloat162 l2[2];
    #pragma unroll
    for (int u = 0; u < 4; u++) {
        float f = (&v.x)[u] + (&bv.x)[u];
        __nv_bfloat16 h = __float2bfloat16_rn(f);
        ((__nv_bfloat16*)h2)[u] = h;
        ((__nv_bfloat16*)l2)[u] = __float2bfloat16_rn(f - __bfloat162float(h));
    }
    reinterpret_cast<__nv_bfloat162*>(hi)[idx*2]   = h2[0];
    reinterpret_cast<__nv_bfloat162*>(hi)[idx*2+1] = h2[1];
    reinterpret_cast<__nv_bfloat162*>(lo)[idx*2]   = l2[0];
    reinterpret_cast<__nv_bfloat162*>(lo)[idx*2+1] = l2[1];
}

__global__ void bias_add_kernel(float* __restrict__ out,
                                const float* __restrict__ bias, int N4) {
    int idx = blockIdx.x * blockDim.x + threadIdx.x;
    float4 v = reinterpret_cast<float4*>(out)[idx];
    float4 b = reinterpret_cast<const float4*>(bias)[idx & (N4 - 1)];
    v.x += b.x; v.y += b.y; v.z += b.z; v.w += b.w;
    reinterpret_cast<float4*>(out)[idx] = v;
}

// ===========================================================================
// GEMM: C[M,N] = (Ah+Al)[M,K] @ (Bh+Bl)[N,K]^T, 3-term, pipelined 2-stage.
// CTA tile 128x128, BK=32, 256 threads, 8 warps (32x64 warp tile). No asm.
// ===========================================================================
#define GSTR 40

struct GemmSmem {
    __nv_bfloat16 Ah[2][128][GSTR];
    __nv_bfloat16 Al[2][128][GSTR];
    __nv_bfloat16 Bh[2][128][GSTR];
    __nv_bfloat16 Bl[2][128][GSTR];
};

__device__ __forceinline__ void gemm_issue_stage(
        GemmSmem* sm, int s, int k0,
        const __nv_bfloat16* Agh, const __nv_bfloat16* Agl,
        const __nv_bfloat16* Bgh, const __nv_bfloat16* Bgl,
        int row0, int col0, int K, int tid) {
    #pragma unroll
    for (int c = tid; c < 512; c += 256) {
        int r = c >> 2;
        int o = (c & 3) * 8;
        size_t ga = (size_t)(row0 + r) * K + k0 + o;
        size_t gb = (size_t)(col0 + r) * K + k0 + o;
        __pipeline_memcpy_async(&sm->Ah[s][r][o], &Agh[ga], 16);
        __pipeline_memcpy_async(&sm->Al[s][r][o], &Agl[ga], 16);
        __pipeline_memcpy_async(&sm->Bh[s][r][o], &Bgh[gb], 16);
        __pipeline_memcpy_async(&sm->Bl[s][r][o], &Bgl[gb], 16);
    }
    __pipeline_commit();
}

__global__ __launch_bounds__(256, 2)
void gemm_ps_kernel(const __nv_bfloat16* __restrict__ Agh,
                    const __nv_bfloat16* __restrict__ Agl,
                    const __nv_bfloat16* __restrict__ Bgh,
                    const __nv_bfloat16* __restrict__ Bgl,
                    float* __restrict__ C,
                    int M, int N, int K) {
    extern __shared__ char smem_raw[];
    GemmSmem* sm = reinterpret_cast<GemmSmem*>(smem_raw);

    const int tid = threadIdx.x;
    const int warp = tid >> 5;
    const int wr = warp >> 1;
    const int wc = warp & 1;
    const int row0 = blockIdx.y * 128;
    const int col0 = blockIdx.x * 128;
    const int nk = K / 32;

    wmma::fragment<wmma::accumulator, 16, 16, 16, float> acc[2][4];
    #pragma unroll
    for (int i = 0; i < 2; i++) {
        #pragma unroll
        for (int j = 0; j < 4; j++) {
            wmma::fill_fragment(acc[i][j], 0.0f);
        }
    }

    gemm_issue_stage(sm, 0, 0, Agh, Agl, Bgh, Bgl, row0, col0, K, tid);

    for (int kt = 0; kt < nk; kt++) {
        if (kt + 1 < nk) {
            gemm_issue_stage(sm, (kt + 1) & 1, (kt + 1) * 32,
                             Agh, Agl, Bgh, Bgl, row0, col0, K, tid);
            __pipeline_wait_prior(1);
        } else {
            __pipeline_wait_prior(0);
        }
        __syncthreads();

        const int s = kt & 1;
        #pragma unroll
        for (int kk = 0; kk < 32; kk += 16) {
            wmma::fragment<wmma::matrix_a, 16, 16, 16, __nv_bfloat16, wmma::row_major> ah[2], al[2];
            #pragma unroll
            for (int i = 0; i < 2; i++) {
                wmma::load_matrix_sync(ah[i], &sm->Ah[s][wr*32 + i*16][kk], GSTR);
                wmma::load_matrix_sync(al[i], &sm->Al[s][wr*32 + i*16][kk], GSTR);
            }
            #pragma unroll
            for (int j = 0; j < 4; j++) {
                wmma::fragment<wmma::matrix_b, 16, 16, 16, __nv_bfloat16, wmma::col_major> bh, bl;
                wmma::load_matrix_sync(bh, &sm->Bh[s][wc*64 + j*16][kk], GSTR);
                wmma::load_matrix_sync(bl, &sm->Bl[s][wc*64 + j*16][kk], GSTR);
                #pragma unroll
                for (int i = 0; i < 2; i++) {
                    wmma::mma_sync(acc[i][j], ah[i], bh, acc[i][j]);
                    wmma::mma_sync(acc[i][j], ah[i], bl, acc[i][j]);
                    wmma::mma_sync(acc[i][j], al[i], bh, acc[i][j]);
                }
            }
        }
        __syncthreads();
    }

    #pragma unroll
    for (int i = 0; i < 2; i++) {
        #pragma unroll
        for (int j = 0; j < 4; j++) {
            float* cp = &C[(size_t)(row0 + wr*32 + i*16) * N + col0 + wc*64 + j*16];
            wmma::store_matrix_sync(cp, acc[i][j], N, wmma::mem_row_major);
        }
    }
}

// ===========================================================================
// Tensor-core flash attention (same structure as the passing R4 kernel).
// Q-tile 128, kv-tile 64, 512 threads. Outputs bf16 hi/lo directly.
// ===========================================================================
#define SB 72
#define SF 68

struct AttnSmem {
    __nv_bfloat16 Qh[128][SB];
    __nv_bfloat16 Ql[128][SB];
    __nv_bfloat16 Kh[64][SB];
    __nv_bfloat16 Kl[64][SB];
    __nv_bfloat16 Vh[64][SB];
    __nv_bfloat16 Vl[64][SB];
    __nv_bfloat16 Ph[128][SB];
    __nv_bfloat16 Pl[128][SB];
    float S[128][SF];
    float O[128][SF];
    float m_s[128];
    float l_s[128];
    float resc[128];
};

__global__ __launch_bounds__(512)
void attn_wmma_kernel(const __nv_bfloat16* __restrict__ qhi,
                      const __nv_bfloat16* __restrict__ qlo,
                      __nv_bfloat16* __restrict__ ohi,
                      __nv_bfloat16* __restrict__ olo) {
    extern __shared__ char smem_raw[];
    AttnSmem& sm = *reinterpret_cast<AttnSmem*>(smem_raw);

    const int qt = gridDim.x - 1 - blockIdx.x;
    const int h  = blockIdx.y;
    const int b  = blockIdx.z;
    const int tid = threadIdx.x;
    const int warp = tid >> 5;
    const int lane = tid & 31;
    const int wr = warp >> 1;
    const int wc = warp & 1;
    const int q0 = qt * 128;

    for (int t = tid; t < 128*8; t += 512) {
        int r = t >> 3;
        int c8 = (t & 7) * 8;
        size_t g = (size_t)(b*SS + q0 + r) * (3*DD) + h*HD + c8;
        *reinterpret_cast<uint4*>(&sm.Qh[r][c8]) = *reinterpret_cast<const uint4*>(&qhi[g]);
        *reinterpret_cast<uint4*>(&sm.Ql[r][c8]) = *reinterpret_cast<const uint4*>(&qlo[g]);
    }
    for (int t = tid; t < 128*16; t += 512) {
        int r = t >> 4;
        int c4 = (t & 15) * 4;
        *reinterpret_cast<float4*>(&sm.O[r][c4]) = make_float4(0.f, 0.f, 0.f, 0.f);
    }
    if (tid < 128) {
        sm.m_s[tid] = -1e30f;
        sm.l_s[tid] = 0.0f;
    }
    __syncthreads();

    const int srow = tid >> 2;
    const int sq   = tid & 3;
    const int cb   = sq * 16;
    const int nkt  = 2*qt + 2;

    for (int kt = 0; kt < nkt; kt++) {
        const int k0 = kt * 64;

        for (int t = tid; t < 64*8; t += 512) {
            int r = t >> 3;
            int c8 = (t & 7) * 8;
            size_t base = (size_t)(b*SS + k0 + r) * (3*DD) + h*HD + c8;
            *reinterpret_cast<uint4*>(&sm.Kh[r][c8]) = *reinterpret_cast<const uint4*>(&qhi[base + DD]);
            *reinterpret_cast<uint4*>(&sm.Kl[r][c8]) = *reinterpret_cast<const uint4*>(&qlo[base + DD]);
            *reinterpret_cast<uint4*>(&sm.Vh[r][c8]) = *reinterpret_cast<const uint4*>(&qhi[base + 2*DD]);
            *reinterpret_cast<uint4*>(&sm.Vl[r][c8]) = *reinterpret_cast<const uint4*>(&qlo[base + 2*DD]);
        }
        __syncthreads();

        {
            wmma::fragment<wmma::accumulator, 16, 16, 16, float> s0, s1;
            wmma::fill_fragment(s0, 0.0f);
            wmma::fill_fragment(s1, 0.0f);
            #pragma unroll
            for (int ks = 0; ks < 4; ks++) {
                int kk = ks * 16;
                wmma::fragment<wmma::matrix_a, 16, 16, 16, __nv_bfloat16, wmma::row_major> ah, al;
                wmma::fragment<wmma::matrix_b, 16, 16, 16, __nv_bfloat16, wmma::col_major> bh0, bh1, bl0, bl1;
                wmma::load_matrix_sync(ah, &sm.Qh[wr*16][kk], SB);
                wmma::load_matrix_sync(al, &sm.Ql[wr*16][kk], SB);
                wmma::load_matrix_sync(bh0, &sm.Kh[wc*32][kk], SB);
                wmma::load_matrix_sync(bh1, &sm.Kh[wc*32+16][kk], SB);
                wmma::load_matrix_sync(bl0, &sm.Kl[wc*32][kk], SB);
                wmma::load_matrix_sync(bl1, &sm.Kl[wc*32+16][kk], SB);
                wmma::mma_sync(s0, ah, bh0, s0);
                wmma::mma_sync(s0, ah, bl0, s0);
                wmma::mma_sync(s0, al, bh0, s0);
                wmma::mma_sync(s1, ah, bh1, s1);
                wmma::mma_sync(s1, ah, bl1, s1);
                wmma::mma_sync(s1, al, bh1, s1);
            }
            wmma::store_matrix_sync(&sm.S[wr*16][wc*32],      s0, SF, wmma::mem_row_major);
            wmma::store_matrix_sync(&sm.S[wr*16][wc*32 + 16], s1, SF, wmma::mem_row_major);
        }
        __syncthreads();

        {
            const bool diag = (kt >= 2*qt);
            float sv[16];
            float mloc = -1e30f;
            #pragma unroll
            for (int c = 0; c < 16; c++) {
                float s = sm.S[srow][cb + c] * 0.125f;
                if (diag && (k0 + cb + c > q0 + srow)) {
                    s = -1e30f;
                }
                sv[c] = s;
                mloc = fmaxf(mloc, s);
            }
            mloc = fmaxf(mloc, __shfl_xor_sync(0xFFFFFFFF, mloc, 1));
            mloc = fmaxf(mloc, __shfl_xor_sync(0xFFFFFFFF, mloc, 2));
            float mold = sm.m_s[srow];
            float nm = fmaxf(mold, mloc);
            float ls = 0.0f;
            #pragma unroll
            for (int c = 0; c < 16; c++) {
                float p = __expf(sv[c] - nm);
                ls += p;
                __nv_bfloat16 ph = __float2bfloat16_rn(p);
                sm.Ph[srow][cb + c] = ph;
                sm.Pl[srow][cb + c] = __float2bfloat16_rn(p - __bfloat162float(ph));
            }
            ls += __shfl_xor_sync(0xFFFFFFFF, ls, 1);
            ls += __shfl_xor_sync(0xFFFFFFFF, ls, 2);
            if (sq == 0) {
                float rs = __expf(mold - nm);
                sm.resc[srow] = rs;
                sm.l_s[srow] = sm.l_s[srow] * rs + ls;
                sm.m_s[srow] = nm;
            }
        }
        __syncthreads();

        {
            wmma::fragment<wmma::accumulator, 16, 16, 16, float> p0, p1;
            wmma::fill_fragment(p0, 0.0f);
            wmma::fill_fragment(p1, 0.0f);
            #pragma unroll
            for (int ks = 0; ks < 4; ks++) {
                int kk = ks * 16;
                wmma::fragment<wmma::matrix_a, 16, 16, 16, __nv_bfloat16, wmma::row_major> ah, al;
                wmma::fragment<wmma::matrix_b, 16, 16, 16, __nv_bfloat16, wmma::row_major> bh0, bh1, bl0, bl1;
                wmma::load_matrix_sync(ah, &sm.Ph[wr*16][kk], SB);
                wmma::load_matrix_sync(al, &sm.Pl[wr*16][kk], SB);
                wmma::load_matrix_sync(bh0, &sm.Vh[kk][wc*32], SB);
                wmma::load_matrix_sync(bh1, &sm.Vh[kk][wc*32+16], SB);
                wmma::load_matrix_sync(bl0, &sm.Vl[kk][wc*32], SB);
                wmma::load_matrix_sync(bl1, &sm.Vl[kk][wc*32+16], SB);
                wmma::mma_sync(p0, ah, bh0, p0);
                wmma::mma_sync(p0, ah, bl0, p0);
                wmma::mma_sync(p0, al, bh0, p0);
                wmma::mma_sync(p1, ah, bh1, p1);
                wmma::mma_sync(p1, ah, bl1, p1);
                wmma::mma_sync(p1, al, bh1, p1);
            }
            wmma::store_matrix_sync(&sm.S[wr*16][wc*32],      p0, SF, wmma::mem_row_major);
            wmma::store_matrix_sync(&sm.S[wr*16][wc*32 + 16], p1, SF, wmma::mem_row_major);
            __syncwarp();
            int r = wr*16 + (lane >> 1);
            int c0 = wc*32 + (lane & 1) * 16;
            float rs = sm.resc[r];
            #pragma unroll
            for (int c = 0; c < 16; c++) {
                sm.O[r][c0 + c] = sm.O[r][c0 + c] * rs + sm.S[r][c0 + c];
            }
        }
        __syncthreads();
    }

    // epilogue: normalize, split to bf16 hi/lo, write [tok][DD]
    {
        float inv = 1.0f / sm.l_s[srow];
        size_t gbase = (size_t)(b*SS + q0 + srow) * DD + h*HD + cb;
        #pragma unroll
        for (int c = 0; c < 16; c += 2) {
            float f0 = sm.O[srow][cb + c] * inv;
            float f1 = sm.O[srow][cb + c + 1] * inv;
            __nv_bfloat162 hv = __floats2bfloat162_rn(f0, f1);
            __nv_bfloat162 lv = __floats2bfloat162_rn(f0 - __bfloat162float(hv.x),
                                                      f1 - __bfloat162float(hv.y));
            *reinterpret_cast<__nv_bfloat162*>(&ohi[gbase + c]) = hv;
            *reinterpret_cast<__nv_bfloat162*>(&olo[gbase + c]) = lv;
        }
    }
}

// ===========================================================================
extern "C" void kernel_launch(void* const* d_in, const int* in_sizes, int n_in,
                              void* d_out, int out_size) {
    const float* x     = (const float*)d_in[0];
    const float* W_qkv = (const float*)d_in[1];
    const float* b_qkv = (const float*)d_in[2];
    const float* W_out = (const float*)d_in[3];
    const float* b_out = (const float*)d_in[4];
    float* out = (float*)d_out;

    float* qkv_ptr;
    __nv_bfloat16* qhi;
    __nv_bfloat16* qlo;
    __nv_bfloat16* xh;
    __nv_bfloat16* xl;
    __nv_bfloat16* wqh;
    __nv_bfloat16* wql;
    __nv_bfloat16* woh;
    __nv_bfloat16* wol;
    __nv_bfloat16* oh;
    __nv_bfloat16* ol;
    cudaGetSymbolAddress((void**)&qkv_ptr, g_qkv);
    cudaGetSymbolAddress((void**)&qhi, g_qkv_hi);
    cudaGetSymbolAddress((void**)&qlo, g_qkv_lo);
    cudaGetSymbolAddress((void**)&xh, g_xh);
    cudaGetSymbolAddress((void**)&xl, g_xl);
    cudaGetSymbolAddress((void**)&wqh, g_wqh);
    cudaGetSymbolAddress((void**)&wql, g_wql);
    cudaGetSymbolAddress((void**)&woh, g_woh);
    cudaGetSymbolAddress((void**)&wol, g_wol);
    cudaGetSymbolAddress((void**)&oh, g_oh);
    cudaGetSymbolAddress((void**)&ol, g_ol);

    cudaFuncSetAttribute(gemm_ps_kernel,
                         cudaFuncAttributeMaxDynamicSharedMemorySize,
                         (int)sizeof(GemmSmem));
    cudaFuncSetAttribute(attn_wmma_kernel,
                         cudaFuncAttributeMaxDynamicSharedMemorySize,
                         (int)sizeof(AttnSmem));

    // 0) split GEMM operands to bf16 hi/lo
    split_nobias_kernel<<<(MTOK*DD/4)/256, 256>>>(x, xh, xl);
    split_nobias_kernel<<<(3*DD*DD/4)/256, 256>>>(W_qkv, wqh, wql);
    split_nobias_kernel<<<(DD*DD/4)/256, 256>>>(W_out, woh, wol);

    // 1) QKV projection: [4096,3072] fp32 (no bias)
    gemm_ps_kernel<<<dim3(3*DD/128, MTOK/128), 256, sizeof(GemmSmem)>>>(
        xh, xl, wqh, wql, qkv_ptr, MTOK, 3*DD, DD);

    // 2) qkv + bias -> bf16 hi/lo
    split_bias_kernel<<<(MTOK*3*DD/4)/256, 256>>>(qkv_ptr, b_qkv, qhi, qlo, 3*DD/4);

    // 3) attention -> bf16 hi/lo [tok][DD]
    attn_wmma_kernel<<<dim3(SS/128, HH, BB), 512, sizeof(AttnSmem)>>>(qhi, qlo, oh, ol);

    // 4) output projection: [4096,1024] fp32
    gemm_ps_kernel<<<dim3(DD/128, MTOK/128), 256, sizeof(GemmSmem)>>>(
        oh, ol, woh, wol, out, MTOK, DD, DD);

    // 5) + b_out
    bias_add_kernel<<<(MTOK*DD/4)/256, 256>>>(out, b_out, DD/4);
}

// round 10
// speedup vs baseline: 2.5874x; 1.0222x over previous
#include <cuda_runtime.h>
#include <cuda_bf16.h>
#include <cuda_fp16.h>
#include <cuda_pipeline.h>
#include <mma.h>
#include <math.h>

using namespace nvcuda;

#define BB 2
#define SS 2048
#define DD 1024
#define HH 16
#define HD 64
#define MTOK (BB*SS)

// Scratch (allocation-free rule: __device__ globals)
__device__ __nv_bfloat16 g_qkv_hi[BB*SS*3*DD];
__device__ __nv_bfloat16 g_qkv_lo[BB*SS*3*DD];
__device__ __nv_bfloat16 g_xh[MTOK*DD];
__device__ __nv_bfloat16 g_xl[MTOK*DD];
__device__ __nv_bfloat16 g_wqh[3*DD*DD];
__device__ __nv_bfloat16 g_wql[3*DD*DD];
__device__ __nv_bfloat16 g_woh[DD*DD];
__device__ __nv_bfloat16 g_wol[DD*DD];
__device__ __nv_bfloat16 g_oh[MTOK*DD];
__device__ __nv_bfloat16 g_ol[MTOK*DD];

// ===========================================================================
// split kernel: fp32 -> bf16 hi/lo
// ===========================================================================
__global__ void split_nobias_kernel(const float* __restrict__ in,
                                    __nv_bfloat16* __restrict__ hi,
                                    __nv_bfloat16* __restrict__ lo) {
    int idx = blockIdx.x * blockDim.x + threadIdx.x;
    float4 v = reinterpret_cast<const float4*>(in)[idx];
    __nv_bfloat162 h2[2];
    __nv_bfloat162 l2[2];
    #pragma unroll
    for (int u = 0; u < 4; u++) {
        float f = (&v.x)[u];
        __nv_bfloat16 h = __float2bfloat16_rn(f);
        ((__nv_bfloat16*)h2)[u] = h;
        ((__nv_bfloat16*)l2)[u] = __float2bfloat16_rn(f - __bfloat162float(h));
    }
    reinterpret_cast<__nv_bfloat162*>(hi)[idx*2]   = h2[0];
    reinterpret_cast<__nv_bfloat162*>(hi)[idx*2+1] = h2[1];
    reinterpret_cast<__nv_bfloat162*>(lo)[idx*2]   = l2[0];
    reinterpret_cast<__nv_bfloat162*>(lo)[idx*2+1] = l2[1];
}

// ===========================================================================
// GEMM: C[M,N] = (Ah+Al)[M,K] @ (Bh+Bl)[N,K]^T + bias, 3-term, pipelined.
// Fused epilogue: either fp32 out (Cf32) or bf16 hi/lo out (Chi/Clo).
// CTA tile 128x128, BK=32, 256 threads, 8 warps (32x64 warp tile).
// ===========================================================================
#define GSTR 40
#define CST 132

struct GemmSmem {
    __nv_bfloat16 Ah[2][128][GSTR];
    __nv_bfloat16 Al[2][128][GSTR];
    __nv_bfloat16 Bh[2][128][GSTR];
    __nv_bfloat16 Bl[2][128][GSTR];
};

__device__ __forceinline__ void gemm_issue_stage(
        GemmSmem* sm, int s, int k0,
        const __nv_bfloat16* Agh, const __nv_bfloat16* Agl,
        const __nv_bfloat16* Bgh, const __nv_bfloat16* Bgl,
        int row0, int col0, int K, int tid) {
    #pragma unroll
    for (int c = tid; c < 512; c += 256) {
        int r = c >> 2;
        int o = (c & 3) * 8;
        size_t ga = (size_t)(row0 + r) * K + k0 + o;
        size_t gb = (size_t)(col0 + r) * K + k0 + o;
        __pipeline_memcpy_async(&sm->Ah[s][r][o], &Agh[ga], 16);
        __pipeline_memcpy_async(&sm->Al[s][r][o], &Agl[ga], 16);
        __pipeline_memcpy_async(&sm->Bh[s][r][o], &Bgh[gb], 16);
        __pipeline_memcpy_async(&sm->Bl[s][r][o], &Bgl[gb], 16);
    }
    __pipeline_commit();
}

__global__ __launch_bounds__(256, 2)
void gemm_ps_kernel(const __nv_bfloat16* __restrict__ Agh,
                    const __nv_bfloat16* __restrict__ Agl,
                    const __nv_bfloat16* __restrict__ Bgh,
                    const __nv_bfloat16* __restrict__ Bgl,
                    float* __restrict__ Cf32,
                    __nv_bfloat16* __restrict__ Chi,
                    __nv_bfloat16* __restrict__ Clo,
                    const float* __restrict__ bias,
                    int M, int N, int K) {
    extern __shared__ char smem_raw[];
    GemmSmem* sm = reinterpret_cast<GemmSmem*>(smem_raw);

    const int tid = threadIdx.x;
    const int warp = tid >> 5;
    const int wr = warp >> 1;
    const int wc = warp & 1;
    const int row0 = blockIdx.y * 128;
    const int col0 = blockIdx.x * 128;
    const int nk = K / 32;

    wmma::fragment<wmma::accumulator, 16, 16, 16, float> acc[2][4];
    #pragma unroll
    for (int i = 0; i < 2; i++) {
        #pragma unroll
        for (int j = 0; j < 4; j++) {
            wmma::fill_fragment(acc[i][j], 0.0f);
        }
    }

    gemm_issue_stage(sm, 0, 0, Agh, Agl, Bgh, Bgl, row0, col0, K, tid);

    for (int kt = 0; kt < nk; kt++) {
        if (kt + 1 < nk) {
            gemm_issue_stage(sm, (kt + 1) & 1, (kt + 1) * 32,
                             Agh, Agl, Bgh, Bgl, row0, col0, K, tid);
            __pipeline_wait_prior(1);
        } else {
            __pipeline_wait_prior(0);
        }
        __syncthreads();

        const int s = kt & 1;
        #pragma unroll
        for (int kk = 0; kk < 32; kk += 16) {
            wmma::fragment<wmma::matrix_a, 16, 16, 16, __nv_bfloat16, wmma::row_major> ah[2], al[2];
            #pragma unroll
            for (int i = 0; i < 2; i++) {
                wmma::load_matrix_sync(ah[i], &sm->Ah[s][wr*32 + i*16][kk], GSTR);
                wmma::load_matrix_sync(al[i], &sm->Al[s][wr*32 + i*16][kk], GSTR);
            }
            #pragma unroll
            for (int j = 0; j < 4; j++) {
                wmma::fragment<wmma::matrix_b, 16, 16, 16, __nv_bfloat16, wmma::col_major> bh, bl;
                wmma::load_matrix_sync(bh, &sm->Bh[s][wc*64 + j*16][kk], GSTR);
                wmma::load_matrix_sync(bl, &sm->Bl[s][wc*64 + j*16][kk], GSTR);
                #pragma unroll
                for (int i = 0; i < 2; i++) {
                    wmma::mma_sync(acc[i][j], ah[i], bh, acc[i][j]);
                    wmma::mma_sync(acc[i][j], ah[i], bl, acc[i][j]);
                    wmma::mma_sync(acc[i][j], al[i], bh, acc[i][j]);
                }
            }
        }
        __syncthreads();
    }

    // ---- fused epilogue: stage acc in smem, add bias, write out ----
    float* stp = reinterpret_cast<float*>(smem_raw);
    #pragma unroll
    for (int i = 0; i < 2; i++) {
        #pragma unroll
        for (int j = 0; j < 4; j++) {
            wmma::store_matrix_sync(&stp[(size_t)(wr*32 + i*16) * CST + wc*64 + j*16],
                                    acc[i][j], CST, wmma::mem_row_major);
        }
    }
    __syncthreads();

    if (Cf32 != nullptr) {
        for (int t = tid; t < 128*32; t += 256) {
            int r = t >> 5;
            int c4 = (t & 31) * 4;
            float4 v = *reinterpret_cast<const float4*>(&stp[r*CST + c4]);
            float4 bv = *reinterpret_cast<const float4*>(&bias[col0 + c4]);
            v.x += bv.x; v.y += bv.y; v.z += bv.z; v.w += bv.w;
            *reinterpret_cast<float4*>(&Cf32[(size_t)(row0 + r) * N + col0 + c4]) = v;
        }
    } else {
        for (int t = tid; t < 128*32; t += 256) {
            int r = t >> 5;
            int c4 = (t & 31) * 4;
            float4 v = *reinterpret_cast<const float4*>(&stp[r*CST + c4]);
            float4 bv = *reinterpret_cast<const float4*>(&bias[col0 + c4]);
            float f0 = v.x + bv.x;
            float f1 = v.y + bv.y;
            float f2 = v.z + bv.z;
            float f3 = v.w + bv.w;
            __nv_bfloat162 h0 = __floats2bfloat162_rn(f0, f1);
            __nv_bfloat162 h1 = __floats2bfloat162_rn(f2, f3);
            __nv_bfloat162 l0 = __floats2bfloat162_rn(f0 - __bfloat162float(h0.x),
                                                      f1 - __bfloat162float(h0.y));
            __nv_bfloat162 l1 = __floats2bfloat162_rn(f2 - __bfloat162float(h1.x),
                                                      f3 - __bfloat162float(h1.y));
            size_t g = (size_t)(row0 + r) * N + col0 + c4;
            *reinterpret_cast<__nv_bfloat162*>(&Chi[g])     = h0;
            *reinterpret_cast<__nv_bfloat162*>(&Chi[g + 2]) = h1;
            *reinterpret_cast<__nv_bfloat162*>(&Clo[g])     = l0;
            *reinterpret_cast<__nv_bfloat162*>(&Clo[g + 2]) = l1;
        }
    }
}

// ===========================================================================
// Tensor-core flash attention. Q-tile 128, kv-tile 64, 512 threads.
// Base-2 softmax with paired fp16 exp (h2exp2): 2 exps per MUFU op.
// ===========================================================================
#define SB 72
#define SF 68

struct AttnSmem {
    __nv_bfloat16 Qh[128][SB];
    __nv_bfloat16 Ql[128][SB];
    __nv_bfloat16 Kh[64][SB];
    __nv_bfloat16 Kl[64][SB];
    __nv_bfloat16 Vh[64][SB];
    __nv_bfloat16 Vl[64][SB];
    __nv_bfloat16 Ph[128][SB];
    __nv_bfloat16 Pl[128][SB];
    float S[128][SF];
    float O[128][SF];
    float m_s[128];
    float l_s[128];
    float resc[128];
};

__global__ __launch_bounds__(512)
void attn_wmma_kernel(const __nv_bfloat16* __restrict__ qhi,
                      const __nv_bfloat16* __restrict__ qlo,
                      __nv_bfloat16* __restrict__ ohi,
                      __nv_bfloat16* __restrict__ olo) {
    extern __shared__ char smem_raw[];
    AttnSmem& sm = *reinterpret_cast<AttnSmem*>(smem_raw);

    const int qt = gridDim.x - 1 - blockIdx.x;
    const int h  = blockIdx.y;
    const int b  = blockIdx.z;
    const int tid = threadIdx.x;
    const int warp = tid >> 5;
    const int lane = tid & 31;
    const int wr = warp >> 1;
    const int wc = warp & 1;
    const int q0 = qt * 128;
    const float CSC = 0.18033688011112042f;   // 0.125 * log2(e)

    for (int t = tid; t < 128*8; t += 512) {
        int r = t >> 3;
        int c8 = (t & 7) * 8;
        size_t g = (size_t)(b*SS + q0 + r) * (3*DD) + h*HD + c8;
        *reinterpret_cast<uint4*>(&sm.Qh[r][c8]) = *reinterpret_cast<const uint4*>(&qhi[g]);
        *reinterpret_cast<uint4*>(&sm.Ql[r][c8]) = *reinterpret_cast<const uint4*>(&qlo[g]);
    }
    for (int t = tid; t < 128*16; t += 512) {
        int r = t >> 4;
        int c4 = (t & 15) * 4;
        *reinterpret_cast<float4*>(&sm.O[r][c4]) = make_float4(0.f, 0.f, 0.f, 0.f);
    }
    if (tid < 128) {
        sm.m_s[tid] = -1e30f;
        sm.l_s[tid] = 0.0f;
    }
    __syncthreads();

    const int srow = tid >> 2;
    const int sq   = tid & 3;
    const int cb   = sq * 16;
    const int nkt  = 2*qt + 2;

    for (int kt = 0; kt < nkt; kt++) {
        const int k0 = kt * 64;

        for (int t = tid; t < 64*8; t += 512) {
            int r = t >> 3;
            int c8 = (t & 7) * 8;
            size_t base = (size_t)(b*SS + k0 + r) * (3*DD) + h*HD + c8;
            *reinterpret_cast<uint4*>(&sm.Kh[r][c8]) = *reinterpret_cast<const uint4*>(&qhi[base + DD]);
            *reinterpret_cast<uint4*>(&sm.Kl[r][c8]) = *reinterpret_cast<const uint4*>(&qlo[base + DD]);
            *reinterpret_cast<uint4*>(&sm.Vh[r][c8]) = *reinterpret_cast<const uint4*>(&qhi[base + 2*DD]);
            *reinterpret_cast<uint4*>(&sm.Vl[r][c8]) = *reinterpret_cast<const uint4*>(&qlo[base + 2*DD]);
        }
        __syncthreads();

        {
            wmma::fragment<wmma::accumulator, 16, 16, 16, float> s0, s1;
            wmma::fill_fragment(s0, 0.0f);
            wmma::fill_fragment(s1, 0.0f);
            #pragma unroll
            for (int ks = 0; ks < 4; ks++) {
                int kk = ks * 16;
                wmma::fragment<wmma::matrix_a, 16, 16, 16, __nv_bfloat16, wmma::row_major> ah, al;
                wmma::fragment<wmma::matrix_b, 16, 16, 16, __nv_bfloat16, wmma::col_major> bh0, bh1, bl0, bl1;
                wmma::load_matrix_sync(ah, &sm.Qh[wr*16][kk], SB);
                wmma::load_matrix_sync(al, &sm.Ql[wr*16][kk], SB);
                wmma::load_matrix_sync(bh0, &sm.Kh[wc*32][kk], SB);
                wmma::load_matrix_sync(bh1, &sm.Kh[wc*32+16][kk], SB);
                wmma::load_matrix_sync(bl0, &sm.Kl[wc*32][kk], SB);
                wmma::load_matrix_sync(bl1, &sm.Kl[wc*32+16][kk], SB);
                wmma::mma_sync(s0, ah, bh0, s0);
                wmma::mma_sync(s0, ah, bl0, s0);
                wmma::mma_sync(s0, al, bh0, s0);
                wmma::mma_sync(s1, ah, bh1, s1);
                wmma::mma_sync(s1, ah, bl1, s1);
                wmma::mma_sync(s1, al, bh1, s1);
            }
            wmma::store_matrix_sync(&sm.S[wr*16][wc*32],      s0, SF, wmma::mem_row_major);
            wmma::store_matrix_sync(&sm.S[wr*16][wc*32 + 16], s1, SF, wmma::mem_row_major);
        }
        __syncthreads();

        // ---- base-2 online softmax, paired fp16 exp ----
        {
            const bool diag = (kt >= 2*qt);
            float sv[16];
            float mloc = -1e30f;
            #pragma unroll
            for (int c4 = 0; c4 < 4; c4++) {
                float4 v = *reinterpret_cast<const float4*>(&sm.S[srow][cb + c4*4]);
                sv[c4*4+0] = v.x * CSC;
                sv[c4*4+1] = v.y * CSC;
                sv[c4*4+2] = v.z * CSC;
                sv[c4*4+3] = v.w * CSC;
            }
            #pragma unroll
            for (int c = 0; c < 16; c++) {
                if (diag && (k0 + cb + c > q0 + srow)) {
                    sv[c] = -1e30f;
                }
                mloc = fmaxf(mloc, sv[c]);
            }
            mloc = fmaxf(mloc, __shfl_xor_sync(0xFFFFFFFF, mloc, 1));
            mloc = fmaxf(mloc, __shfl_xor_sync(0xFFFFFFFF, mloc, 2));
            float mold = sm.m_s[srow];
            float nm = fmaxf(mold, mloc);
            float ls = 0.0f;
            #pragma unroll
            for (int c = 0; c < 16; c += 2) {
                __half2 dh = __floats2half2_rn(sv[c] - nm, sv[c+1] - nm);
                __half2 p2 = h2exp2(dh);
                float2 pf = __half22float2(p2);
                ls += pf.x + pf.y;
                __nv_bfloat162 ph = __floats2bfloat162_rn(pf.x, pf.y);
                *reinterpret_cast<__nv_bfloat162*>(&sm.Ph[srow][cb + c]) = ph;
                __nv_bfloat162 pl = __floats2bfloat162_rn(pf.x - __bfloat162float(ph.x),
                                                          pf.y - __bfloat162float(ph.y));
                *reinterpret_cast<__nv_bfloat162*>(&sm.Pl[srow][cb + c]) = pl;
            }
            ls += __shfl_xor_sync(0xFFFFFFFF, ls, 1);
            ls += __shfl_xor_sync(0xFFFFFFFF, ls, 2);
            if (sq == 0) {
                float rs = exp2f(mold - nm);
                sm.resc[srow] = rs;
                sm.l_s[srow] = sm.l_s[srow] * rs + ls;
                sm.m_s[srow] = nm;
            }
        }
        __syncthreads();

        {
            wmma::fragment<wmma::accumulator, 16, 16, 16, float> p0, p1;
            wmma::fill_fragment(p0, 0.0f);
            wmma::fill_fragment(p1, 0.0f);
            #pragma unroll
            for (int ks = 0; ks < 4; ks++) {
                int kk = ks * 16;
                wmma::fragment<wmma::matrix_a, 16, 16, 16, __nv_bfloat16, wmma::row_major> ah, al;
                wmma::fragment<wmma::matrix_b, 16, 16, 16, __nv_bfloat16, wmma::row_major> bh0, bh1, bl0, bl1;
                wmma::load_matrix_sync(ah, &sm.Ph[wr*16][kk], SB);
                wmma::load_matrix_sync(al, &sm.Pl[wr*16][kk], SB);
                wmma::load_matrix_sync(bh0, &sm.Vh[kk][wc*32], SB);
                wmma::load_matrix_sync(bh1, &sm.Vh[kk][wc*32+16], SB);
                wmma::load_matrix_sync(bl0, &sm.Vl[kk][wc*32], SB);
                wmma::load_matrix_sync(bl1, &sm.Vl[kk][wc*32+16], SB);
                wmma::mma_sync(p0, ah, bh0, p0);
                wmma::mma_sync(p0, ah, bl0, p0);
                wmma::mma_sync(p0, al, bh0, p0);
                wmma::mma_sync(p1, ah, bh1, p1);
                wmma::mma_sync(p1, ah, bl1, p1);
                wmma::mma_sync(p1, al, bh1, p1);
            }
            wmma::store_matrix_sync(&sm.S[wr*16][wc*32],      p0, SF, wmma::mem_row_major);
            wmma::store_matrix_sync(&sm.S[wr*16][wc*32 + 16], p1, SF, wmma::mem_row_major);
            __syncwarp();
            int r = wr*16 + (lane >> 1);
            int c0 = wc*32 + (lane & 1) * 16;
            float rs = sm.resc[r];
            #pragma unroll
            for (int c = 0; c < 16; c++) {
                sm.O[r][c0 + c] = sm.O[r][c0 + c] * rs + sm.S[r][c0 + c];
            }
        }
        __syncthreads();
    }

    // epilogue: normalize, split to bf16 hi/lo, write [tok][DD]
    {
        float inv = 1.0f / sm.l_s[srow];
        size_t gbase = (size_t)(b*SS + q0 + srow) * DD + h*HD + cb;
        #pragma unroll
        for (int c = 0; c < 16; c += 2) {
            float f0 = sm.O[srow][cb + c] * inv;
            float f1 = sm.O[srow][cb + c + 1] * inv;
            __nv_bfloat162 hv = __floats2bfloat162_rn(f0, f1);
            __nv_bfloat162 lv = __floats2bfloat162_rn(f0 - __bfloat162float(hv.x),
                                                      f1 - __bfloat162float(hv.y));
            *reinterpret_cast<__nv_bfloat162*>(&ohi[gbase + c]) = hv;
            *reinterpret_cast<__nv_bfloat162*>(&olo[gbase + c]) = lv;
        }
    }
}

// ===========================================================================
extern "C" void kernel_launch(void* const* d_in, const int* in_sizes, int n_in,
                              void* d_out, int out_size) {
    const float* x     = (const float*)d_in[0];
    const float* W_qkv = (const float*)d_in[1];
    const float* b_qkv = (const float*)d_in[2];
    const float* W_out = (const float*)d_in[3];
    const float* b_out = (const float*)d_in[4];
    float* out = (float*)d_out;

    __nv_bfloat16* qhi;
    __nv_bfloat16* qlo;
    __nv_bfloat16* xh;
    __nv_bfloat16* xl;
    __nv_bfloat16* wqh;
    __nv_bfloat16* wql;
    __nv_bfloat16* woh;
    __nv_bfloat16* wol;
    __nv_bfloat16* oh;
    __nv_bfloat16* ol;
    cudaGetSymbolAddress((void**)&qhi, g_qkv_hi);
    cudaGetSymbolAddress((void**)&qlo, g_qkv_lo);
    cudaGetSymbolAddress((void**)&xh, g_xh);
    cudaGetSymbolAddress((void**)&xl, g_xl);
    cudaGetSymbolAddress((void**)&wqh, g_wqh);
    cudaGetSymbolAddress((void**)&wql, g_wql);
    cudaGetSymbolAddress((void**)&woh, g_woh);
    cudaGetSymbolAddress((void**)&wol, g_wol);
    cudaGetSymbolAddress((void**)&oh, g_oh);
    cudaGetSymbolAddress((void**)&ol, g_ol);

    cudaFuncSetAttribute(gemm_ps_kernel,
                         cudaFuncAttributeMaxDynamicSharedMemorySize,
                         (int)sizeof(GemmSmem));
    cudaFuncSetAttribute(attn_wmma_kernel,
                         cudaFuncAttributeMaxDynamicSharedMemorySize,
                         (int)sizeof(AttnSmem));

    // 0) split GEMM operands to bf16 hi/lo
    split_nobias_kernel<<<(MTOK*DD/4)/256, 256>>>(x, xh, xl);
    split_nobias_kernel<<<(3*DD*DD/4)/256, 256>>>(W_qkv, wqh, wql);
    split_nobias_kernel<<<(DD*DD/4)/256, 256>>>(W_out, woh, wol);

    // 1) QKV projection + bias, fused output as bf16 hi/lo [tok][3D]
    gemm_ps_kernel<<<dim3(3*DD/128, MTOK/128), 256, sizeof(GemmSmem)>>>(
        xh, xl, wqh, wql, nullptr, qhi, qlo, b_qkv, MTOK, 3*DD, DD);

    // 2) attention -> bf16 hi/lo [tok][DD]
    attn_wmma_kernel<<<dim3(SS/128, HH, BB), 512, sizeof(AttnSmem)>>>(qhi, qlo, oh, ol);

    // 3) output projection + bias -> fp32 out
    gemm_ps_kernel<<<dim3(DD/128, MTOK/128), 256, sizeof(GemmSmem)>>>(
        oh, ol, woh, wol, out, nullptr, nullptr, b_out, MTOK, DD, DD);
}

// round 11
// speedup vs baseline: 3.2430x; 1.2534x over previous
#include <cuda_runtime.h>
#include <cuda_fp16.h>
#include <cuda_pipeline.h>
#include <mma.h>
#include <math.h>

using namespace nvcuda;

#define BB 2
#define SS 2048
#define DD 1024
#define HH 16
#define HD 64
#define MTOK (BB*SS)

// Scratch (allocation-free rule: __device__ globals)
__device__ __half g_qkv_hi[BB*SS*3*DD];
__device__ __half g_qkv_lo[BB*SS*3*DD];
__device__ __half g_xh[MTOK*DD];
__device__ __half g_xl[MTOK*DD];
__device__ __half g_wqh[3*DD*DD];
__device__ __half g_wql[3*DD*DD];
__device__ __half g_woh[DD*DD];
__device__ __half g_wol[DD*DD];
__device__ __half g_oh[MTOK*DD];
__device__ __half g_ol[MTOK*DD];

// ===========================================================================
// split kernel: fp32 -> fp16 hi/lo
// ===========================================================================
__global__ void split_nobias_kernel(const float* __restrict__ in,
                                    __half* __restrict__ hi,
                                    __half* __restrict__ lo) {
    int idx = blockIdx.x * blockDim.x + threadIdx.x;
    float4 v = reinterpret_cast<const float4*>(in)[idx];
    __half2 h2[2];
    __half2 l2[2];
    #pragma unroll
    for (int u = 0; u < 4; u++) {
        float f = (&v.x)[u];
        __half h = __float2half_rn(f);
        ((__half*)h2)[u] = h;
        ((__half*)l2)[u] = __float2half_rn(f - __half2float(h));
    }
    reinterpret_cast<__half2*>(hi)[idx*2]   = h2[0];
    reinterpret_cast<__half2*>(hi)[idx*2+1] = h2[1];
    reinterpret_cast<__half2*>(lo)[idx*2]   = l2[0];
    reinterpret_cast<__half2*>(lo)[idx*2+1] = l2[1];
}

// ===========================================================================
// GEMM: C[M,N] = (Ah+Al)[M,K] @ (Bh+Bl)[N,K]^T + bias, 3-term fp16 split,
// pipelined 2-stage. CTA tile 128x128, BK=32, 256 threads, 8 warps.
// MMA order interleaved so same-acc MMAs are >=3 apart (hide HMMA latency).
// ===========================================================================
#define GSTR 40
#define CST 132

struct GemmSmem {
    __half Ah[2][128][GSTR];
    __half Al[2][128][GSTR];
    __half Bh[2][128][GSTR];
    __half Bl[2][128][GSTR];
};

__device__ __forceinline__ void gemm_issue_stage(
        GemmSmem* sm, int s, int k0,
        const __half* Agh, const __half* Agl,
        const __half* Bgh, const __half* Bgl,
        int row0, int col0, int K, int tid) {
    #pragma unroll
    for (int c = tid; c < 512; c += 256) {
        int r = c >> 2;
        int o = (c & 3) * 8;
        size_t ga = (size_t)(row0 + r) * K + k0 + o;
        size_t gb = (size_t)(col0 + r) * K + k0 + o;
        __pipeline_memcpy_async(&sm->Ah[s][r][o], &Agh[ga], 16);
        __pipeline_memcpy_async(&sm->Al[s][r][o], &Agl[ga], 16);
        __pipeline_memcpy_async(&sm->Bh[s][r][o], &Bgh[gb], 16);
        __pipeline_memcpy_async(&sm->Bl[s][r][o], &Bgl[gb], 16);
    }
    __pipeline_commit();
}

__global__ __launch_bounds__(256, 2)
void gemm_ps_kernel(const __half* __restrict__ Agh,
                    const __half* __restrict__ Agl,
                    const __half* __restrict__ Bgh,
                    const __half* __restrict__ Bgl,
                    float* __restrict__ Cf32,
                    __half* __restrict__ Chi,
                    __half* __restrict__ Clo,
                    const float* __restrict__ bias,
                    int M, int N, int K) {
    extern __shared__ char smem_raw[];
    GemmSmem* sm = reinterpret_cast<GemmSmem*>(smem_raw);

    const int tid = threadIdx.x;
    const int warp = tid >> 5;
    const int wr = warp >> 1;
    const int wc = warp & 1;
    const int row0 = blockIdx.y * 128;
    const int col0 = blockIdx.x * 128;
    const int nk = K / 32;

    wmma::fragment<wmma::accumulator, 16, 16, 16, float> acc[2][4];
    #pragma unroll
    for (int i = 0; i < 2; i++) {
        #pragma unroll
        for (int j = 0; j < 4; j++) {
            wmma::fill_fragment(acc[i][j], 0.0f);
        }
    }

    gemm_issue_stage(sm, 0, 0, Agh, Agl, Bgh, Bgl, row0, col0, K, tid);

    for (int kt = 0; kt < nk; kt++) {
        if (kt + 1 < nk) {
            gemm_issue_stage(sm, (kt + 1) & 1, (kt + 1) * 32,
                             Agh, Agl, Bgh, Bgl, row0, col0, K, tid);
            __pipeline_wait_prior(1);
        } else {
            __pipeline_wait_prior(0);
        }
        __syncthreads();

        const int s = kt & 1;
        #pragma unroll
        for (int kk = 0; kk < 32; kk += 16) {
            wmma::fragment<wmma::matrix_a, 16, 16, 16, half, wmma::row_major> ah[2], al[2];
            #pragma unroll
            for (int i = 0; i < 2; i++) {
                wmma::load_matrix_sync(ah[i], &sm->Ah[s][wr*32 + i*16][kk], GSTR);
                wmma::load_matrix_sync(al[i], &sm->Al[s][wr*32 + i*16][kk], GSTR);
            }
            #pragma unroll
            for (int jp = 0; jp < 2; jp++) {
                const int j0 = jp * 2;
                const int j1 = j0 + 1;
                wmma::fragment<wmma::matrix_b, 16, 16, 16, half, wmma::col_major> bh0, bh1, bl0, bl1;
                wmma::load_matrix_sync(bh0, &sm->Bh[s][wc*64 + j0*16][kk], GSTR);
                wmma::load_matrix_sync(bh1, &sm->Bh[s][wc*64 + j1*16][kk], GSTR);
                wmma::load_matrix_sync(bl0, &sm->Bl[s][wc*64 + j0*16][kk], GSTR);
                wmma::load_matrix_sync(bl1, &sm->Bl[s][wc*64 + j1*16][kk], GSTR);
                // interleaved: same-acc MMAs are 4 apart
                wmma::mma_sync(acc[0][j0], ah[0], bh0, acc[0][j0]);
                wmma::mma_sync(acc[1][j0], ah[1], bh0, acc[1][j0]);
                wmma::mma_sync(acc[0][j1], ah[0], bh1, acc[0][j1]);
                wmma::mma_sync(acc[1][j1], ah[1], bh1, acc[1][j1]);
                wmma::mma_sync(acc[0][j0], ah[0], bl0, acc[0][j0]);
                wmma::mma_sync(acc[1][j0], ah[1], bl0, acc[1][j0]);
                wmma::mma_sync(acc[0][j1], ah[0], bl1, acc[0][j1]);
                wmma::mma_sync(acc[1][j1], ah[1], bl1, acc[1][j1]);
                wmma::mma_sync(acc[0][j0], al[0], bh0, acc[0][j0]);
                wmma::mma_sync(acc[1][j0], al[1], bh0, acc[1][j0]);
                wmma::mma_sync(acc[0][j1], al[0], bh1, acc[0][j1]);
                wmma::mma_sync(acc[1][j1], al[1], bh1, acc[1][j1]);
            }
        }
        __syncthreads();
    }

    // ---- fused epilogue: stage acc in smem, add bias, write out ----
    float* stp = reinterpret_cast<float*>(smem_raw);
    #pragma unroll
    for (int i = 0; i < 2; i++) {
        #pragma unroll
        for (int j = 0; j < 4; j++) {
            wmma::store_matrix_sync(&stp[(size_t)(wr*32 + i*16) * CST + wc*64 + j*16],
                                    acc[i][j], CST, wmma::mem_row_major);
        }
    }
    __syncthreads();

    if (Cf32 != nullptr) {
        for (int t = tid; t < 128*32; t += 256) {
            int r = t >> 5;
            int c4 = (t & 31) * 4;
            float4 v = *reinterpret_cast<const float4*>(&stp[r*CST + c4]);
            float4 bv = *reinterpret_cast<const float4*>(&bias[col0 + c4]);
            v.x += bv.x; v.y += bv.y; v.z += bv.z; v.w += bv.w;
            *reinterpret_cast<float4*>(&Cf32[(size_t)(row0 + r) * N + col0 + c4]) = v;
        }
    } else {
        for (int t = tid; t < 128*32; t += 256) {
            int r = t >> 5;
            int c4 = (t & 31) * 4;
            float4 v = *reinterpret_cast<const float4*>(&stp[r*CST + c4]);
            float4 bv = *reinterpret_cast<const float4*>(&bias[col0 + c4]);
            float f0 = v.x + bv.x;
            float f1 = v.y + bv.y;
            float f2 = v.z + bv.z;
            float f3 = v.w + bv.w;
            __half2 h0 = __floats2half2_rn(f0, f1);
            __half2 h1 = __floats2half2_rn(f2, f3);
            __half2 l0 = __floats2half2_rn(f0 - __half2float(h0.x),
                                           f1 - __half2float(h0.y));
            __half2 l1 = __floats2half2_rn(f2 - __half2float(h1.x),
                                           f3 - __half2float(h1.y));
            size_t g = (size_t)(row0 + r) * N + col0 + c4;
            *reinterpret_cast<__half2*>(&Chi[g])     = h0;
            *reinterpret_cast<__half2*>(&Chi[g + 2]) = h1;
            *reinterpret_cast<__half2*>(&Clo[g])     = l0;
            *reinterpret_cast<__half2*>(&Clo[g + 2]) = l1;
        }
    }
}

// ===========================================================================
// Tensor-core flash attention. Q-tile 128, kv-tile 64, 512 threads.
// QK^T: 3-term fp16 split. P: raw fp16 from h2exp2 (consistent with l-sum).
// PV: SINGLE-term fp16 (P fp16 x V fp16).
// ===========================================================================
#define SB 72
#define SF 68

struct AttnSmem {
    __half Qh[128][SB];
    __half Ql[128][SB];
    __half Kh[64][SB];
    __half Kl[64][SB];
    __half Vh[64][SB];
    __half Ph[128][SB];
    float S[128][SF];
    float O[128][SF];
    float m_s[128];
    float l_s[128];
    float resc[128];
};

__global__ __launch_bounds__(512)
void attn_wmma_kernel(const __half* __restrict__ qhi,
                      const __half* __restrict__ qlo,
                      __half* __restrict__ ohi,
                      __half* __restrict__ olo) {
    extern __shared__ char smem_raw[];
    AttnSmem& sm = *reinterpret_cast<AttnSmem*>(smem_raw);

    const int qt = gridDim.x - 1 - blockIdx.x;
    const int h  = blockIdx.y;
    const int b  = blockIdx.z;
    const int tid = threadIdx.x;
    const int warp = tid >> 5;
    const int lane = tid & 31;
    const int wr = warp >> 1;
    const int wc = warp & 1;
    const int q0 = qt * 128;
    const float CSC = 0.18033688011112042f;   // 0.125 * log2(e)

    for (int t = tid; t < 128*8; t += 512) {
        int r = t >> 3;
        int c8 = (t & 7) * 8;
        size_t g = (size_t)(b*SS + q0 + r) * (3*DD) + h*HD + c8;
        *reinterpret_cast<uint4*>(&sm.Qh[r][c8]) = *reinterpret_cast<const uint4*>(&qhi[g]);
        *reinterpret_cast<uint4*>(&sm.Ql[r][c8]) = *reinterpret_cast<const uint4*>(&qlo[g]);
    }
    for (int t = tid; t < 128*16; t += 512) {
        int r = t >> 4;
        int c4 = (t & 15) * 4;
        *reinterpret_cast<float4*>(&sm.O[r][c4]) = make_float4(0.f, 0.f, 0.f, 0.f);
    }
    if (tid < 128) {
        sm.m_s[tid] = -1e30f;
        sm.l_s[tid] = 0.0f;
    }
    __syncthreads();

    const int srow = tid >> 2;
    const int sq   = tid & 3;
    const int cb   = sq * 16;
    const int nkt  = 2*qt + 2;

    for (int kt = 0; kt < nkt; kt++) {
        const int k0 = kt * 64;

        // K hi/lo + V hi only (PV is single-term)
        for (int t = tid; t < 64*8; t += 512) {
            int r = t >> 3;
            int c8 = (t & 7) * 8;
            size_t base = (size_t)(b*SS + k0 + r) * (3*DD) + h*HD + c8;
            *reinterpret_cast<uint4*>(&sm.Kh[r][c8]) = *reinterpret_cast<const uint4*>(&qhi[base + DD]);
            *reinterpret_cast<uint4*>(&sm.Kl[r][c8]) = *reinterpret_cast<const uint4*>(&qlo[base + DD]);
            *reinterpret_cast<uint4*>(&sm.Vh[r][c8]) = *reinterpret_cast<const uint4*>(&qhi[base + 2*DD]);
        }
        __syncthreads();

        {
            wmma::fragment<wmma::accumulator, 16, 16, 16, float> s0, s1;
            wmma::fill_fragment(s0, 0.0f);
            wmma::fill_fragment(s1, 0.0f);
            #pragma unroll
            for (int ks = 0; ks < 4; ks++) {
                int kk = ks * 16;
                wmma::fragment<wmma::matrix_a, 16, 16, 16, half, wmma::row_major> ah, al;
                wmma::fragment<wmma::matrix_b, 16, 16, 16, half, wmma::col_major> bh0, bh1, bl0, bl1;
                wmma::load_matrix_sync(ah, &sm.Qh[wr*16][kk], SB);
                wmma::load_matrix_sync(al, &sm.Ql[wr*16][kk], SB);
                wmma::load_matrix_sync(bh0, &sm.Kh[wc*32][kk], SB);
                wmma::load_matrix_sync(bh1, &sm.Kh[wc*32+16][kk], SB);
                wmma::load_matrix_sync(bl0, &sm.Kl[wc*32][kk], SB);
                wmma::load_matrix_sync(bl1, &sm.Kl[wc*32+16][kk], SB);
                wmma::mma_sync(s0, ah, bh0, s0);
                wmma::mma_sync(s1, ah, bh1, s1);
                wmma::mma_sync(s0, ah, bl0, s0);
                wmma::mma_sync(s1, ah, bl1, s1);
                wmma::mma_sync(s0, al, bh0, s0);
                wmma::mma_sync(s1, al, bh1, s1);
            }
            wmma::store_matrix_sync(&sm.S[wr*16][wc*32],      s0, SF, wmma::mem_row_major);
            wmma::store_matrix_sync(&sm.S[wr*16][wc*32 + 16], s1, SF, wmma::mem_row_major);
        }
        __syncthreads();

        // ---- base-2 online softmax; P stored as raw fp16 (h2exp2 output) ----
        {
            const bool diag = (kt >= 2*qt);
            float sv[16];
            float mloc = -1e30f;
            #pragma unroll
            for (int c4 = 0; c4 < 4; c4++) {
                float4 v = *reinterpret_cast<const float4*>(&sm.S[srow][cb + c4*4]);
                sv[c4*4+0] = v.x * CSC;
                sv[c4*4+1] = v.y * CSC;
                sv[c4*4+2] = v.z * CSC;
                sv[c4*4+3] = v.w * CSC;
            }
            #pragma unroll
            for (int c = 0; c < 16; c++) {
                if (diag && (k0 + cb + c > q0 + srow)) {
                    sv[c] = -1e30f;
                }
                mloc = fmaxf(mloc, sv[c]);
            }
            mloc = fmaxf(mloc, __shfl_xor_sync(0xFFFFFFFF, mloc, 1));
            mloc = fmaxf(mloc, __shfl_xor_sync(0xFFFFFFFF, mloc, 2));
            float mold = sm.m_s[srow];
            float nm = fmaxf(mold, mloc);
            float ls = 0.0f;
            #pragma unroll
            for (int c = 0; c < 16; c += 2) {
                __half2 dh = __floats2half2_rn(sv[c] - nm, sv[c+1] - nm);
                __half2 p2 = h2exp2(dh);
                *reinterpret_cast<__half2*>(&sm.Ph[srow][cb + c]) = p2;
                float2 pf = __half22float2(p2);
                ls += pf.x + pf.y;
            }
            ls += __shfl_xor_sync(0xFFFFFFFF, ls, 1);
            ls += __shfl_xor_sync(0xFFFFFFFF, ls, 2);
            if (sq == 0) {
                float rs = exp2f(mold - nm);
                sm.resc[srow] = rs;
                sm.l_s[srow] = sm.l_s[srow] * rs + ls;
                sm.m_s[srow] = nm;
            }
        }
        __syncthreads();

        // ---- PV: single-term fp16 ----
        {
            wmma::fragment<wmma::accumulator, 16, 16, 16, float> p0, p1;
            wmma::fill_fragment(p0, 0.0f);
            wmma::fill_fragment(p1, 0.0f);
            #pragma unroll
            for (int ks = 0; ks < 4; ks++) {
                int kk = ks * 16;
                wmma::fragment<wmma::matrix_a, 16, 16, 16, half, wmma::row_major> ah;
                wmma::fragment<wmma::matrix_b, 16, 16, 16, half, wmma::row_major> bh0, bh1;
                wmma::load_matrix_sync(ah, &sm.Ph[wr*16][kk], SB);
                wmma::load_matrix_sync(bh0, &sm.Vh[kk][wc*32], SB);
                wmma::load_matrix_sync(bh1, &sm.Vh[kk][wc*32+16], SB);
                wmma::mma_sync(p0, ah, bh0, p0);
                wmma::mma_sync(p1, ah, bh1, p1);
            }
            wmma::store_matrix_sync(&sm.S[wr*16][wc*32],      p0, SF, wmma::mem_row_major);
            wmma::store_matrix_sync(&sm.S[wr*16][wc*32 + 16], p1, SF, wmma::mem_row_major);
            __syncwarp();
            int r = wr*16 + (lane >> 1);
            int c0 = wc*32 + (lane & 1) * 16;
            float rs = sm.resc[r];
            #pragma unroll
            for (int c = 0; c < 16; c++) {
                sm.O[r][c0 + c] = sm.O[r][c0 + c] * rs + sm.S[r][c0 + c];
            }
        }
        __syncthreads();
    }

    // epilogue: normalize, split to fp16 hi/lo, write [tok][DD]
    {
        float inv = 1.0f / sm.l_s[srow];
        size_t gbase = (size_t)(b*SS + q0 + srow) * DD + h*HD + cb;
        #pragma unroll
        for (int c = 0; c < 16; c += 2) {
            float f0 = sm.O[srow][cb + c] * inv;
            float f1 = sm.O[srow][cb + c + 1] * inv;
            __half2 hv = __floats2half2_rn(f0, f1);
            __half2 lv = __floats2half2_rn(f0 - __half2float(hv.x),
                                           f1 - __half2float(hv.y));
            *reinterpret_cast<__half2*>(&ohi[gbase + c]) = hv;
            *reinterpret_cast<__half2*>(&olo[gbase + c]) = lv;
        }
    }
}

// ===========================================================================
extern "C" void kernel_launch(void* const* d_in, const int* in_sizes, int n_in,
                              void* d_out, int out_size) {
    const float* x     = (const float*)d_in[0];
    const float* W_qkv = (const float*)d_in[1];
    const float* b_qkv = (const float*)d_in[2];
    const float* W_out = (const float*)d_in[3];
    const float* b_out = (const float*)d_in[4];
    float* out = (float*)d_out;

    __half* qhi;
    __half* qlo;
    __half* xh;
    __half* xl;
    __half* wqh;
    __half* wql;
    __half* woh;
    __half* wol;
    __half* oh;
    __half* ol;
    cudaGetSymbolAddress((void**)&qhi, g_qkv_hi);
    cudaGetSymbolAddress((void**)&qlo, g_qkv_lo);
    cudaGetSymbolAddress((void**)&xh, g_xh);
    cudaGetSymbolAddress((void**)&xl, g_xl);
    cudaGetSymbolAddress((void**)&wqh, g_wqh);
    cudaGetSymbolAddress((void**)&wql, g_wql);
    cudaGetSymbolAddress((void**)&woh, g_woh);
    cudaGetSymbolAddress((void**)&wol, g_wol);
    cudaGetSymbolAddress((void**)&oh, g_oh);
    cudaGetSymbolAddress((void**)&ol, g_ol);

    cudaFuncSetAttribute(gemm_ps_kernel,
                         cudaFuncAttributeMaxDynamicSharedMemorySize,
                         (int)sizeof(GemmSmem));
    cudaFuncSetAttribute(attn_wmma_kernel,
                         cudaFuncAttributeMaxDynamicSharedMemorySize,
                         (int)sizeof(AttnSmem));

    // 0) split GEMM operands to fp16 hi/lo
    split_nobias_kernel<<<(MTOK*DD/4)/256, 256>>>(x, xh, xl);
    split_nobias_kernel<<<(3*DD*DD/4)/256, 256>>>(W_qkv, wqh, wql);
    split_nobias_kernel<<<(DD*DD/4)/256, 256>>>(W_out, woh, wol);

    // 1) QKV projection + bias, fused output as fp16 hi/lo [tok][3D]
    gemm_ps_kernel<<<dim3(3*DD/128, MTOK/128), 256, sizeof(GemmSmem)>>>(
        xh, xl, wqh, wql, nullptr, qhi, qlo, b_qkv, MTOK, 3*DD, DD);

    // 2) attention -> fp16 hi/lo [tok][DD]
    attn_wmma_kernel<<<dim3(SS/128, HH, BB), 512, sizeof(AttnSmem)>>>(qhi, qlo, oh, ol);

    // 3) output projection + bias -> fp32 out
    gemm_ps_kernel<<<dim3(DD/128, MTOK/128), 256, sizeof(GemmSmem)>>>(
        oh, ol, woh, wol, out, nullptr, nullptr, b_out, MTOK, DD, DD);
}

// round 13
// speedup vs baseline: 3.9157x; 1.2074x over previous
#include <cuda_runtime.h>
#include <cuda_fp16.h>
#include <cuda_pipeline.h>
#include <mma.h>
#include <math.h>

using namespace nvcuda;

#define BB 2
#define SS 2048
#define DD 1024
#define HH 16
#define HD 64
#define MTOK (BB*SS)

// Scratch (allocation-free rule: __device__ globals)
__device__ __half g_qkv_hi[BB*SS*3*DD];
__device__ __half g_qkv_lo[BB*SS*3*DD];
__device__ __half g_xh[MTOK*DD];
__device__ __half g_wqh[3*DD*DD];
__device__ __half g_wql[3*DD*DD];
__device__ __half g_woh[DD*DD];
__device__ __half g_wol[DD*DD];
__device__ __half g_oh[MTOK*DD];

// ===========================================================================
// split kernels
// ===========================================================================
__global__ void split_nobias_kernel(const float* __restrict__ in,
                                    __half* __restrict__ hi,
                                    __half* __restrict__ lo) {
    int idx = blockIdx.x * blockDim.x + threadIdx.x;
    float4 v = reinterpret_cast<const float4*>(in)[idx];
    __half2 h2[2];
    __half2 l2[2];
    #pragma unroll
    for (int u = 0; u < 4; u++) {
        float f = (&v.x)[u];
        __half h = __float2half_rn(f);
        ((__half*)h2)[u] = h;
        ((__half*)l2)[u] = __float2half_rn(f - __half2float(h));
    }
    reinterpret_cast<__half2*>(hi)[idx*2]   = h2[0];
    reinterpret_cast<__half2*>(hi)[idx*2+1] = h2[1];
    reinterpret_cast<__half2*>(lo)[idx*2]   = l2[0];
    reinterpret_cast<__half2*>(lo)[idx*2+1] = l2[1];
}

__global__ void split_hi_kernel(const float* __restrict__ in,
                                __half* __restrict__ hi) {
    int idx = blockIdx.x * blockDim.x + threadIdx.x;
    float4 v = reinterpret_cast<const float4*>(in)[idx];
    __half2 h2[2];
    h2[0] = __floats2half2_rn(v.x, v.y);
    h2[1] = __floats2half2_rn(v.z, v.w);
    reinterpret_cast<__half2*>(hi)[idx*2]   = h2[0];
    reinterpret_cast<__half2*>(hi)[idx*2+1] = h2[1];
}

// ===========================================================================
// GEMM: C[M,N] = Ah[M,K] @ (Bh+Bl)[N,K]^T + bias  (2-term fp16 split),
// pipelined 2-stage. CTA tile 128x128, BK=32, 256 threads, 8 warps.
// Dynamic smem = max(mainloop staging, fp32 epilogue staging 128*CST).
// ===========================================================================
#define GSTR 40
#define CST 132

struct GemmSmem {
    __half Ah[2][128][GSTR];
    __half Bh[2][128][GSTR];
    __half Bl[2][128][GSTR];
};

// epilogue needs 128*CST floats = 67584 B > sizeof(GemmSmem) = 61440 B
#define GEMM_SMEM_BYTES (128 * CST * 4)

__device__ __forceinline__ void gemm_issue_stage(
        GemmSmem* sm, int s, int k0,
        const __half* Agh,
        const __half* Bgh, const __half* Bgl,
        int row0, int col0, int K, int tid) {
    #pragma unroll
    for (int c = tid; c < 512; c += 256) {
        int r = c >> 2;
        int o = (c & 3) * 8;
        size_t ga = (size_t)(row0 + r) * K + k0 + o;
        size_t gb = (size_t)(col0 + r) * K + k0 + o;
        __pipeline_memcpy_async(&sm->Ah[s][r][o], &Agh[ga], 16);
        __pipeline_memcpy_async(&sm->Bh[s][r][o], &Bgh[gb], 16);
        __pipeline_memcpy_async(&sm->Bl[s][r][o], &Bgl[gb], 16);
    }
    __pipeline_commit();
}

__global__ __launch_bounds__(256, 2)
void gemm_ps_kernel(const __half* __restrict__ Agh,
                    const __half* __restrict__ Bgh,
                    const __half* __restrict__ Bgl,
                    float* __restrict__ Cf32,
                    __half* __restrict__ Chi,
                    __half* __restrict__ Clo,
                    const float* __restrict__ bias,
                    int M, int N, int K) {
    extern __shared__ char smem_raw[];
    GemmSmem* sm = reinterpret_cast<GemmSmem*>(smem_raw);

    const int tid = threadIdx.x;
    const int warp = tid >> 5;
    const int wr = warp >> 1;
    const int wc = warp & 1;
    const int row0 = blockIdx.y * 128;
    const int col0 = blockIdx.x * 128;
    const int nk = K / 32;

    wmma::fragment<wmma::accumulator, 16, 16, 16, float> acc[2][4];
    #pragma unroll
    for (int i = 0; i < 2; i++) {
        #pragma unroll
        for (int j = 0; j < 4; j++) {
            wmma::fill_fragment(acc[i][j], 0.0f);
        }
    }

    gemm_issue_stage(sm, 0, 0, Agh, Bgh, Bgl, row0, col0, K, tid);

    for (int kt = 0; kt < nk; kt++) {
        if (kt + 1 < nk) {
            gemm_issue_stage(sm, (kt + 1) & 1, (kt + 1) * 32,
                             Agh, Bgh, Bgl, row0, col0, K, tid);
            __pipeline_wait_prior(1);
        } else {
            __pipeline_wait_prior(0);
        }
        __syncthreads();

        const int s = kt & 1;
        #pragma unroll
        for (int kk = 0; kk < 32; kk += 16) {
            wmma::fragment<wmma::matrix_a, 16, 16, 16, half, wmma::row_major> ah[2];
            wmma::load_matrix_sync(ah[0], &sm->Ah[s][wr*32][kk], GSTR);
            wmma::load_matrix_sync(ah[1], &sm->Ah[s][wr*32 + 16][kk], GSTR);
            #pragma unroll
            for (int jp = 0; jp < 2; jp++) {
                const int j0 = jp * 2;
                const int j1 = j0 + 1;
                wmma::fragment<wmma::matrix_b, 16, 16, 16, half, wmma::col_major> bh0, bh1, bl0, bl1;
                wmma::load_matrix_sync(bh0, &sm->Bh[s][wc*64 + j0*16][kk], GSTR);
                wmma::load_matrix_sync(bh1, &sm->Bh[s][wc*64 + j1*16][kk], GSTR);
                wmma::load_matrix_sync(bl0, &sm->Bl[s][wc*64 + j0*16][kk], GSTR);
                wmma::load_matrix_sync(bl1, &sm->Bl[s][wc*64 + j1*16][kk], GSTR);
                // interleaved: same-acc MMAs are 4 apart
                wmma::mma_sync(acc[0][j0], ah[0], bh0, acc[0][j0]);
                wmma::mma_sync(acc[1][j0], ah[1], bh0, acc[1][j0]);
                wmma::mma_sync(acc[0][j1], ah[0], bh1, acc[0][j1]);
                wmma::mma_sync(acc[1][j1], ah[1], bh1, acc[1][j1]);
                wmma::mma_sync(acc[0][j0], ah[0], bl0, acc[0][j0]);
                wmma::mma_sync(acc[1][j0], ah[1], bl0, acc[1][j0]);
                wmma::mma_sync(acc[0][j1], ah[0], bl1, acc[0][j1]);
                wmma::mma_sync(acc[1][j1], ah[1], bl1, acc[1][j1]);
            }
        }
        __syncthreads();
    }

    // ---- fused epilogue: stage acc in smem, add bias, write out ----
    float* stp = reinterpret_cast<float*>(smem_raw);
    #pragma unroll
    for (int i = 0; i < 2; i++) {
        #pragma unroll
        for (int j = 0; j < 4; j++) {
            wmma::store_matrix_sync(&stp[(size_t)(wr*32 + i*16) * CST + wc*64 + j*16],
                                    acc[i][j], CST, wmma::mem_row_major);
        }
    }
    __syncthreads();

    if (Cf32 != nullptr) {
        for (int t = tid; t < 128*32; t += 256) {
            int r = t >> 5;
            int c4 = (t & 31) * 4;
            float4 v = *reinterpret_cast<const float4*>(&stp[r*CST + c4]);
            float4 bv = *reinterpret_cast<const float4*>(&bias[col0 + c4]);
            v.x += bv.x; v.y += bv.y; v.z += bv.z; v.w += bv.w;
            *reinterpret_cast<float4*>(&Cf32[(size_t)(row0 + r) * N + col0 + c4]) = v;
        }
    } else {
        for (int t = tid; t < 128*32; t += 256) {
            int r = t >> 5;
            int c4 = (t & 31) * 4;
            float4 v = *reinterpret_cast<const float4*>(&stp[r*CST + c4]);
            float4 bv = *reinterpret_cast<const float4*>(&bias[col0 + c4]);
            float f0 = v.x + bv.x;
            float f1 = v.y + bv.y;
            float f2 = v.z + bv.z;
            float f3 = v.w + bv.w;
            __half2 h0 = __floats2half2_rn(f0, f1);
            __half2 h1 = __floats2half2_rn(f2, f3);
            __half2 l0 = __floats2half2_rn(f0 - __half2float(h0.x),
                                           f1 - __half2float(h0.y));
            __half2 l1 = __floats2half2_rn(f2 - __half2float(h1.x),
                                           f3 - __half2float(h1.y));
            size_t g = (size_t)(row0 + r) * N + col0 + c4;
            *reinterpret_cast<__half2*>(&Chi[g])     = h0;
            *reinterpret_cast<__half2*>(&Chi[g + 2]) = h1;
            *reinterpret_cast<__half2*>(&Clo[g])     = l0;
            *reinterpret_cast<__half2*>(&Clo[g + 2]) = l1;
        }
    }
}

// ===========================================================================
// Tensor-core flash attention. Q-tile 128, kv-tile 64, 512 threads.
// QK^T: 2-term (Qh x (Kh+Kl)). P raw fp16 from h2exp2. PV single-term fp16,
// accumulated directly into smem O via wmma accumulator load/store.
// ===========================================================================
#define SB 72
#define SF 68

struct AttnSmem {
    __half Qh[128][SB];
    __half Kh[64][SB];
    __half Kl[64][SB];
    __half Vh[64][SB];
    __half Ph[128][SB];
    float S[128][SF];
    float O[128][SF];
    float m_s[128];
    float l_s[128];
    float resc[128];
};

__global__ __launch_bounds__(512)
void attn_wmma_kernel(const __half* __restrict__ qhi,
                      const __half* __restrict__ qlo,
                      __half* __restrict__ ohi) {
    extern __shared__ char smem_raw[];
    AttnSmem& sm = *reinterpret_cast<AttnSmem*>(smem_raw);

    const int qt = gridDim.x - 1 - blockIdx.x;
    const int h  = blockIdx.y;
    const int b  = blockIdx.z;
    const int tid = threadIdx.x;
    const int warp = tid >> 5;
    const int lane = tid & 31;
    const int wr = warp >> 1;
    const int wc = warp & 1;
    const int q0 = qt * 128;
    const float CSC = 0.18033688011112042f;   // 0.125 * log2(e)

    for (int t = tid; t < 128*8; t += 512) {
        int r = t >> 3;
        int c8 = (t & 7) * 8;
        size_t g = (size_t)(b*SS + q0 + r) * (3*DD) + h*HD + c8;
        *reinterpret_cast<uint4*>(&sm.Qh[r][c8]) = *reinterpret_cast<const uint4*>(&qhi[g]);
    }
    for (int t = tid; t < 128*16; t += 512) {
        int r = t >> 4;
        int c4 = (t & 15) * 4;
        *reinterpret_cast<float4*>(&sm.O[r][c4]) = make_float4(0.f, 0.f, 0.f, 0.f);
    }
    if (tid < 128) {
        sm.m_s[tid] = -1e30f;
        sm.l_s[tid] = 0.0f;
    }
    __syncthreads();

    const int srow = tid >> 2;
    const int sq   = tid & 3;
    const int cb   = sq * 16;
    const int nkt  = 2*qt + 2;

    for (int kt = 0; kt < nkt; kt++) {
        const int k0 = kt * 64;

        for (int t = tid; t < 64*8; t += 512) {
            int r = t >> 3;
            int c8 = (t & 7) * 8;
            size_t base = (size_t)(b*SS + k0 + r) * (3*DD) + h*HD + c8;
            *reinterpret_cast<uint4*>(&sm.Kh[r][c8]) = *reinterpret_cast<const uint4*>(&qhi[base + DD]);
            *reinterpret_cast<uint4*>(&sm.Kl[r][c8]) = *reinterpret_cast<const uint4*>(&qlo[base + DD]);
            *reinterpret_cast<uint4*>(&sm.Vh[r][c8]) = *reinterpret_cast<const uint4*>(&qhi[base + 2*DD]);
        }
        __syncthreads();

        // ---- S = Qh @ (Kh + Kl)^T ----
        {
            wmma::fragment<wmma::accumulator, 16, 16, 16, float> s0, s1;
            wmma::fill_fragment(s0, 0.0f);
            wmma::fill_fragment(s1, 0.0f);
            #pragma unroll
            for (int ks = 0; ks < 4; ks++) {
                int kk = ks * 16;
                wmma::fragment<wmma::matrix_a, 16, 16, 16, half, wmma::row_major> ah;
                wmma::fragment<wmma::matrix_b, 16, 16, 16, half, wmma::col_major> bh0, bh1, bl0, bl1;
                wmma::load_matrix_sync(ah, &sm.Qh[wr*16][kk], SB);
                wmma::load_matrix_sync(bh0, &sm.Kh[wc*32][kk], SB);
                wmma::load_matrix_sync(bh1, &sm.Kh[wc*32+16][kk], SB);
                wmma::load_matrix_sync(bl0, &sm.Kl[wc*32][kk], SB);
                wmma::load_matrix_sync(bl1, &sm.Kl[wc*32+16][kk], SB);
                wmma::mma_sync(s0, ah, bh0, s0);
                wmma::mma_sync(s1, ah, bh1, s1);
                wmma::mma_sync(s0, ah, bl0, s0);
                wmma::mma_sync(s1, ah, bl1, s1);
            }
            wmma::store_matrix_sync(&sm.S[wr*16][wc*32],      s0, SF, wmma::mem_row_major);
            wmma::store_matrix_sync(&sm.S[wr*16][wc*32 + 16], s1, SF, wmma::mem_row_major);
        }
        __syncthreads();

        // ---- base-2 online softmax; P stored as raw fp16 (h2exp2 output) ----
        {
            const bool diag = (kt >= 2*qt);
            float sv[16];
            float mloc = -1e30f;
            #pragma unroll
            for (int c4 = 0; c4 < 4; c4++) {
                float4 v = *reinterpret_cast<const float4*>(&sm.S[srow][cb + c4*4]);
                sv[c4*4+0] = v.x * CSC;
                sv[c4*4+1] = v.y * CSC;
                sv[c4*4+2] = v.z * CSC;
                sv[c4*4+3] = v.w * CSC;
            }
            #pragma unroll
            for (int c = 0; c < 16; c++) {
                if (diag && (k0 + cb + c > q0 + srow)) {
                    sv[c] = -1e30f;
                }
                mloc = fmaxf(mloc, sv[c]);
            }
            mloc = fmaxf(mloc, __shfl_xor_sync(0xFFFFFFFF, mloc, 1));
            mloc = fmaxf(mloc, __shfl_xor_sync(0xFFFFFFFF, mloc, 2));
            float mold = sm.m_s[srow];
            float nm = fmaxf(mold, mloc);
            float ls = 0.0f;
            #pragma unroll
            for (int c = 0; c < 16; c += 2) {
                __half2 dh = __floats2half2_rn(sv[c] - nm, sv[c+1] - nm);
                __half2 p2 = h2exp2(dh);
                *reinterpret_cast<__half2*>(&sm.Ph[srow][cb + c]) = p2;
                float2 pf = __half22float2(p2);
                ls += pf.x + pf.y;
            }
            ls += __shfl_xor_sync(0xFFFFFFFF, ls, 1);
            ls += __shfl_xor_sync(0xFFFFFFFF, ls, 2);
            if (sq == 0) {
                float rs = exp2f(mold - nm);
                sm.resc[srow] = rs;
                sm.l_s[srow] = sm.l_s[srow] * rs + ls;
                sm.m_s[srow] = nm;
            }
        }
        __syncthreads();

        // ---- PV: single-term fp16, accumulate directly into O ----
        {
            // warp-private O slab: rescale rows by resc, then use as accumulator
            int r = wr*16 + (lane >> 1);
            int c0 = wc*32 + (lane & 1) * 16;
            float rs = sm.resc[r];
            #pragma unroll
            for (int c = 0; c < 16; c += 4) {
                float4 v = *reinterpret_cast<const float4*>(&sm.O[r][c0 + c]);
                v.x *= rs; v.y *= rs; v.z *= rs; v.w *= rs;
                *reinterpret_cast<float4*>(&sm.O[r][c0 + c]) = v;
            }
            __syncwarp();

            wmma::fragment<wmma::accumulator, 16, 16, 16, float> p0, p1;
            wmma::load_matrix_sync(p0, &sm.O[wr*16][wc*32],      SF, wmma::mem_row_major);
            wmma::load_matrix_sync(p1, &sm.O[wr*16][wc*32 + 16], SF, wmma::mem_row_major);
            #pragma unroll
            for (int ks = 0; ks < 4; ks++) {
                int kk = ks * 16;
                wmma::fragment<wmma::matrix_a, 16, 16, 16, half, wmma::row_major> ah;
                wmma::fragment<wmma::matrix_b, 16, 16, 16, half, wmma::row_major> bh0, bh1;
                wmma::load_matrix_sync(ah, &sm.Ph[wr*16][kk], SB);
                wmma::load_matrix_sync(bh0, &sm.Vh[kk][wc*32], SB);
                wmma::load_matrix_sync(bh1, &sm.Vh[kk][wc*32+16], SB);
                wmma::mma_sync(p0, ah, bh0, p0);
                wmma::mma_sync(p1, ah, bh1, p1);
            }
            wmma::store_matrix_sync(&sm.O[wr*16][wc*32],      p0, SF, wmma::mem_row_major);
            wmma::store_matrix_sync(&sm.O[wr*16][wc*32 + 16], p1, SF, wmma::mem_row_major);
        }
        __syncthreads();
    }

    // epilogue: normalize, write fp16 hi to [tok][DD]
    {
        float inv = 1.0f / sm.l_s[srow];
        size_t gbase = (size_t)(b*SS + q0 + srow) * DD + h*HD + cb;
        #pragma unroll
        for (int c = 0; c < 16; c += 2) {
            float f0 = sm.O[srow][cb + c] * inv;
            float f1 = sm.O[srow][cb + c + 1] * inv;
            *reinterpret_cast<__half2*>(&ohi[gbase + c]) = __floats2half2_rn(f0, f1);
        }
    }
}

// ===========================================================================
extern "C" void kernel_launch(void* const* d_in, const int* in_sizes, int n_in,
                              void* d_out, int out_size) {
    const float* x     = (const float*)d_in[0];
    const float* W_qkv = (const float*)d_in[1];
    const float* b_qkv = (const float*)d_in[2];
    const float* W_out = (const float*)d_in[3];
    const float* b_out = (const float*)d_in[4];
    float* out = (float*)d_out;

    __half* qhi;
    __half* qlo;
    __half* xh;
    __half* wqh;
    __half* wql;
    __half* woh;
    __half* wol;
    __half* oh;
    cudaGetSymbolAddress((void**)&qhi, g_qkv_hi);
    cudaGetSymbolAddress((void**)&qlo, g_qkv_lo);
    cudaGetSymbolAddress((void**)&xh, g_xh);
    cudaGetSymbolAddress((void**)&wqh, g_wqh);
    cudaGetSymbolAddress((void**)&wql, g_wql);
    cudaGetSymbolAddress((void**)&woh, g_woh);
    cudaGetSymbolAddress((void**)&wol, g_wol);
    cudaGetSymbolAddress((void**)&oh, g_oh);

    cudaFuncSetAttribute(gemm_ps_kernel,
                         cudaFuncAttributeMaxDynamicSharedMemorySize,
                         GEMM_SMEM_BYTES);
    cudaFuncSetAttribute(attn_wmma_kernel,
                         cudaFuncAttributeMaxDynamicSharedMemorySize,
                         (int)sizeof(AttnSmem));

    // 0) splits: x -> hi only; weights -> hi/lo
    split_hi_kernel<<<(MTOK*DD/4)/256, 256>>>(x, xh);
    split_nobias_kernel<<<(3*DD*DD/4)/256, 256>>>(W_qkv, wqh, wql);
    split_nobias_kernel<<<(DD*DD/4)/256, 256>>>(W_out, woh, wol);

    // 1) QKV projection + bias -> fp16 hi/lo [tok][3D]
    gemm_ps_kernel<<<dim3(3*DD/128, MTOK/128), 256, GEMM_SMEM_BYTES>>>(
        xh, wqh, wql, nullptr, qhi, qlo, b_qkv, MTOK, 3*DD, DD);

    // 2) attention -> fp16 hi [tok][DD]
    attn_wmma_kernel<<<dim3(SS/128, HH, BB), 512, sizeof(AttnSmem)>>>(qhi, qlo, oh);

    // 3) output projection + bias -> fp32 out
    gemm_ps_kernel<<<dim3(DD/128, MTOK/128), 256, GEMM_SMEM_BYTES>>>(
        oh, woh, wol, out, nullptr, nullptr, b_out, MTOK, DD, DD);
}

// round 15
// speedup vs baseline: 4.1303x; 1.0548x over previous
#include <cuda_runtime.h>
#include <cuda_fp16.h>
#include <cuda_pipeline.h>
#include <mma.h>
#include <math.h>

using namespace nvcuda;

#define BB 2
#define SS 2048
#define DD 1024
#define HH 16
#define HD 64
#define MTOK (BB*SS)

// Scratch (allocation-free rule: __device__ globals)
__device__ __half g_qkv_hi[BB*SS*3*DD];
__device__ __half g_qkv_lo[BB*SS*3*DD];
__device__ __half g_xh[MTOK*DD];
__device__ __half g_wqh[3*DD*DD];
__device__ __half g_wql[3*DD*DD];
__device__ __half g_woh[DD*DD];
__device__ __half g_wol[DD*DD];
__device__ __half g_oh[MTOK*DD];

// ===========================================================================
// split kernels
// ===========================================================================
__global__ void split_nobias_kernel(const float* __restrict__ in,
                                    __half* __restrict__ hi,
                                    __half* __restrict__ lo) {
    int idx = blockIdx.x * blockDim.x + threadIdx.x;
    float4 v = reinterpret_cast<const float4*>(in)[idx];
    __half2 h2[2];
    __half2 l2[2];
    #pragma unroll
    for (int u = 0; u < 4; u++) {
        float f = (&v.x)[u];
        __half h = __float2half_rn(f);
        ((__half*)h2)[u] = h;
        ((__half*)l2)[u] = __float2half_rn(f - __half2float(h));
    }
    reinterpret_cast<__half2*>(hi)[idx*2]   = h2[0];
    reinterpret_cast<__half2*>(hi)[idx*2+1] = h2[1];
    reinterpret_cast<__half2*>(lo)[idx*2]   = l2[0];
    reinterpret_cast<__half2*>(lo)[idx*2+1] = l2[1];
}

__global__ void split_hi_kernel(const float* __restrict__ in,
                                __half* __restrict__ hi) {
    int idx = blockIdx.x * blockDim.x + threadIdx.x;
    float4 v = reinterpret_cast<const float4*>(in)[idx];
    __half2 h2[2];
    h2[0] = __floats2half2_rn(v.x, v.y);
    h2[1] = __floats2half2_rn(v.z, v.w);
    reinterpret_cast<__half2*>(hi)[idx*2]   = h2[0];
    reinterpret_cast<__half2*>(hi)[idx*2+1] = h2[1];
}

// ===========================================================================
// GEMM: C[M,N] = Ah[M,K] @ (Bh+Bl)[N,K]^T + bias  (2-term fp16 split),
// pipelined 2-stage, BK=64. CTA tile 128x128, 256 threads, 8 warps.
// ===========================================================================
#define GSTR 72
#define CST 132

struct GemmSmem {
    __half Ah[2][128][GSTR];
    __half Bh[2][128][GSTR];
    __half Bl[2][128][GSTR];
};

// sizeof(GemmSmem) = 110592 > epilogue staging (128*CST*4 = 67584)
#define GEMM_SMEM_BYTES ((int)sizeof(GemmSmem))

__device__ __forceinline__ void gemm_issue_stage(
        GemmSmem* sm, int s, int k0,
        const __half* Agh,
        const __half* Bgh, const __half* Bgl,
        int row0, int col0, int K, int tid) {
    #pragma unroll
    for (int c = tid; c < 1024; c += 256) {
        int r = c >> 3;
        int o = (c & 7) * 8;
        size_t ga = (size_t)(row0 + r) * K + k0 + o;
        size_t gb = (size_t)(col0 + r) * K + k0 + o;
        __pipeline_memcpy_async(&sm->Ah[s][r][o], &Agh[ga], 16);
        __pipeline_memcpy_async(&sm->Bh[s][r][o], &Bgh[gb], 16);
        __pipeline_memcpy_async(&sm->Bl[s][r][o], &Bgl[gb], 16);
    }
    __pipeline_commit();
}

__global__ __launch_bounds__(256, 2)
void gemm_ps_kernel(const __half* __restrict__ Agh,
                    const __half* __restrict__ Bgh,
                    const __half* __restrict__ Bgl,
                    float* __restrict__ Cf32,
                    __half* __restrict__ Chi,
                    __half* __restrict__ Clo,
                    const float* __restrict__ bias,
                    int M, int N, int K) {
    extern __shared__ char smem_raw[];
    GemmSmem* sm = reinterpret_cast<GemmSmem*>(smem_raw);

    const int tid = threadIdx.x;
    const int warp = tid >> 5;
    const int wr = warp >> 1;
    const int wc = warp & 1;
    const int row0 = blockIdx.y * 128;
    const int col0 = blockIdx.x * 128;
    const int nk = K / 64;

    wmma::fragment<wmma::accumulator, 16, 16, 16, float> acc[2][4];
    #pragma unroll
    for (int i = 0; i < 2; i++) {
        #pragma unroll
        for (int j = 0; j < 4; j++) {
            wmma::fill_fragment(acc[i][j], 0.0f);
        }
    }

    gemm_issue_stage(sm, 0, 0, Agh, Bgh, Bgl, row0, col0, K, tid);

    for (int kt = 0; kt < nk; kt++) {
        if (kt + 1 < nk) {
            gemm_issue_stage(sm, (kt + 1) & 1, (kt + 1) * 64,
                             Agh, Bgh, Bgl, row0, col0, K, tid);
            __pipeline_wait_prior(1);
        } else {
            __pipeline_wait_prior(0);
        }
        __syncthreads();

        const int s = kt & 1;
        #pragma unroll
        for (int kk = 0; kk < 64; kk += 16) {
            wmma::fragment<wmma::matrix_a, 16, 16, 16, half, wmma::row_major> ah[2];
            wmma::load_matrix_sync(ah[0], &sm->Ah[s][wr*32][kk], GSTR);
            wmma::load_matrix_sync(ah[1], &sm->Ah[s][wr*32 + 16][kk], GSTR);
            #pragma unroll
            for (int jp = 0; jp < 2; jp++) {
                const int j0 = jp * 2;
                const int j1 = j0 + 1;
                wmma::fragment<wmma::matrix_b, 16, 16, 16, half, wmma::col_major> bh0, bh1, bl0, bl1;
                wmma::load_matrix_sync(bh0, &sm->Bh[s][wc*64 + j0*16][kk], GSTR);
                wmma::load_matrix_sync(bh1, &sm->Bh[s][wc*64 + j1*16][kk], GSTR);
                wmma::load_matrix_sync(bl0, &sm->Bl[s][wc*64 + j0*16][kk], GSTR);
                wmma::load_matrix_sync(bl1, &sm->Bl[s][wc*64 + j1*16][kk], GSTR);
                // interleaved: same-acc MMAs are 4 apart
                wmma::mma_sync(acc[0][j0], ah[0], bh0, acc[0][j0]);
                wmma::mma_sync(acc[1][j0], ah[1], bh0, acc[1][j0]);
                wmma::mma_sync(acc[0][j1], ah[0], bh1, acc[0][j1]);
                wmma::mma_sync(acc[1][j1], ah[1], bh1, acc[1][j1]);
                wmma::mma_sync(acc[0][j0], ah[0], bl0, acc[0][j0]);
                wmma::mma_sync(acc[1][j0], ah[1], bl0, acc[1][j0]);
                wmma::mma_sync(acc[0][j1], ah[0], bl1, acc[0][j1]);
                wmma::mma_sync(acc[1][j1], ah[1], bl1, acc[1][j1]);
            }
        }
        __syncthreads();
    }

    // ---- fused epilogue: stage acc in smem, add bias, write out ----
    float* stp = reinterpret_cast<float*>(smem_raw);
    #pragma unroll
    for (int i = 0; i < 2; i++) {
        #pragma unroll
        for (int j = 0; j < 4; j++) {
            wmma::store_matrix_sync(&stp[(size_t)(wr*32 + i*16) * CST + wc*64 + j*16],
                                    acc[i][j], CST, wmma::mem_row_major);
        }
    }
    __syncthreads();

    if (Cf32 != nullptr) {
        for (int t = tid; t < 128*32; t += 256) {
            int r = t >> 5;
            int c4 = (t & 31) * 4;
            float4 v = *reinterpret_cast<const float4*>(&stp[r*CST + c4]);
            float4 bv = *reinterpret_cast<const float4*>(&bias[col0 + c4]);
            v.x += bv.x; v.y += bv.y; v.z += bv.z; v.w += bv.w;
            *reinterpret_cast<float4*>(&Cf32[(size_t)(row0 + r) * N + col0 + c4]) = v;
        }
    } else {
        for (int t = tid; t < 128*32; t += 256) {
            int r = t >> 5;
            int c4 = (t & 31) * 4;
            float4 v = *reinterpret_cast<const float4*>(&stp[r*CST + c4]);
            float4 bv = *reinterpret_cast<const float4*>(&bias[col0 + c4]);
            float f0 = v.x + bv.x;
            float f1 = v.y + bv.y;
            float f2 = v.z + bv.z;
            float f3 = v.w + bv.w;
            __half2 h0 = __floats2half2_rn(f0, f1);
            __half2 h1 = __floats2half2_rn(f2, f3);
            __half2 l0 = __floats2half2_rn(f0 - __half2float(h0.x),
                                           f1 - __half2float(h0.y));
            __half2 l1 = __floats2half2_rn(f2 - __half2float(h1.x),
                                           f3 - __half2float(h1.y));
            size_t g = (size_t)(row0 + r) * N + col0 + c4;
            *reinterpret_cast<__half2*>(&Chi[g])     = h0;
            *reinterpret_cast<__half2*>(&Chi[g + 2]) = h1;
            *reinterpret_cast<__half2*>(&Clo[g])     = l0;
            *reinterpret_cast<__half2*>(&Clo[g + 2]) = l1;
        }
    }
}

// ===========================================================================
// Tensor-core flash attention (R12 passing version). Q-tile 128, kv-tile 64,
// 512 threads. QK^T 2-term, P raw fp16 from h2exp2, PV single-term fp16
// accumulated directly into smem O.
// ===========================================================================
#define SB 72
#define SF 68

struct AttnSmem {
    __half Qh[128][SB];
    __half Kh[64][SB];
    __half Kl[64][SB];
    __half Vh[64][SB];
    __half Ph[128][SB];
    float S[128][SF];
    float O[128][SF];
    float m_s[128];
    float l_s[128];
    float resc[128];
};

__global__ __launch_bounds__(512)
void attn_wmma_kernel(const __half* __restrict__ qhi,
                      const __half* __restrict__ qlo,
                      __half* __restrict__ ohi) {
    extern __shared__ char smem_raw[];
    AttnSmem& sm = *reinterpret_cast<AttnSmem*>(smem_raw);

    const int qt = gridDim.x - 1 - blockIdx.x;
    const int h  = blockIdx.y;
    const int b  = blockIdx.z;
    const int tid = threadIdx.x;
    const int warp = tid >> 5;
    const int lane = tid & 31;
    const int wr = warp >> 1;
    const int wc = warp & 1;
    const int q0 = qt * 128;
    const float CSC = 0.18033688011112042f;   // 0.125 * log2(e)

    for (int t = tid; t < 128*8; t += 512) {
        int r = t >> 3;
        int c8 = (t & 7) * 8;
        size_t g = (size_t)(b*SS + q0 + r) * (3*DD) + h*HD + c8;
        *reinterpret_cast<uint4*>(&sm.Qh[r][c8]) = *reinterpret_cast<const uint4*>(&qhi[g]);
    }
    for (int t = tid; t < 128*16; t += 512) {
        int r = t >> 4;
        int c4 = (t & 15) * 4;
        *reinterpret_cast<float4*>(&sm.O[r][c4]) = make_float4(0.f, 0.f, 0.f, 0.f);
    }
    if (tid < 128) {
        sm.m_s[tid] = -1e30f;
        sm.l_s[tid] = 0.0f;
    }
    __syncthreads();

    const int srow = tid >> 2;
    const int sq   = tid & 3;
    const int cb   = sq * 16;
    const int nkt  = 2*qt + 2;

    for (int kt = 0; kt < nkt; kt++) {
        const int k0 = kt * 64;

        for (int t = tid; t < 64*8; t += 512) {
            int r = t >> 3;
            int c8 = (t & 7) * 8;
            size_t base = (size_t)(b*SS + k0 + r) * (3*DD) + h*HD + c8;
            *reinterpret_cast<uint4*>(&sm.Kh[r][c8]) = *reinterpret_cast<const uint4*>(&qhi[base + DD]);
            *reinterpret_cast<uint4*>(&sm.Kl[r][c8]) = *reinterpret_cast<const uint4*>(&qlo[base + DD]);
            *reinterpret_cast<uint4*>(&sm.Vh[r][c8]) = *reinterpret_cast<const uint4*>(&qhi[base + 2*DD]);
        }
        __syncthreads();

        // ---- S = Qh @ (Kh + Kl)^T ----
        {
            wmma::fragment<wmma::accumulator, 16, 16, 16, float> s0, s1;
            wmma::fill_fragment(s0, 0.0f);
            wmma::fill_fragment(s1, 0.0f);
            #pragma unroll
            for (int ks = 0; ks < 4; ks++) {
                int kk = ks * 16;
                wmma::fragment<wmma::matrix_a, 16, 16, 16, half, wmma::row_major> ah;
                wmma::fragment<wmma::matrix_b, 16, 16, 16, half, wmma::col_major> bh0, bh1, bl0, bl1;
                wmma::load_matrix_sync(ah, &sm.Qh[wr*16][kk], SB);
                wmma::load_matrix_sync(bh0, &sm.Kh[wc*32][kk], SB);
                wmma::load_matrix_sync(bh1, &sm.Kh[wc*32+16][kk], SB);
                wmma::load_matrix_sync(bl0, &sm.Kl[wc*32][kk], SB);
                wmma::load_matrix_sync(bl1, &sm.Kl[wc*32+16][kk], SB);
                wmma::mma_sync(s0, ah, bh0, s0);
                wmma::mma_sync(s1, ah, bh1, s1);
                wmma::mma_sync(s0, ah, bl0, s0);
                wmma::mma_sync(s1, ah, bl1, s1);
            }
            wmma::store_matrix_sync(&sm.S[wr*16][wc*32],      s0, SF, wmma::mem_row_major);
            wmma::store_matrix_sync(&sm.S[wr*16][wc*32 + 16], s1, SF, wmma::mem_row_major);
        }
        __syncthreads();

        // ---- base-2 online softmax; P stored as raw fp16 (h2exp2 output) ----
        {
            const bool diag = (kt >= 2*qt);
            float sv[16];
            float mloc = -1e30f;
            #pragma unroll
            for (int c4 = 0; c4 < 4; c4++) {
                float4 v = *reinterpret_cast<const float4*>(&sm.S[srow][cb + c4*4]);
                sv[c4*4+0] = v.x * CSC;
                sv[c4*4+1] = v.y * CSC;
                sv[c4*4+2] = v.z * CSC;
                sv[c4*4+3] = v.w * CSC;
            }
            #pragma unroll
            for (int c = 0; c < 16; c++) {
                if (diag && (k0 + cb + c > q0 + srow)) {
                    sv[c] = -1e30f;
                }
                mloc = fmaxf(mloc, sv[c]);
            }
            mloc = fmaxf(mloc, __shfl_xor_sync(0xFFFFFFFF, mloc, 1));
            mloc = fmaxf(mloc, __shfl_xor_sync(0xFFFFFFFF, mloc, 2));
            float mold = sm.m_s[srow];
            float nm = fmaxf(mold, mloc);
            float ls = 0.0f;
            #pragma unroll
            for (int c = 0; c < 16; c += 2) {
                __half2 dh = __floats2half2_rn(sv[c] - nm, sv[c+1] - nm);
                __half2 p2 = h2exp2(dh);
                *reinterpret_cast<__half2*>(&sm.Ph[srow][cb + c]) = p2;
                float2 pf = __half22float2(p2);
                ls += pf.x + pf.y;
            }
            ls += __shfl_xor_sync(0xFFFFFFFF, ls, 1);
            ls += __shfl_xor_sync(0xFFFFFFFF, ls, 2);
            if (sq == 0) {
                float rs = exp2f(mold - nm);
                sm.resc[srow] = rs;
                sm.l_s[srow] = sm.l_s[srow] * rs + ls;
                sm.m_s[srow] = nm;
            }
        }
        __syncthreads();

        // ---- PV: single-term fp16, accumulate directly into O ----
        {
            int r = wr*16 + (lane >> 1);
            int c0 = wc*32 + (lane & 1) * 16;
            float rs = sm.resc[r];
            #pragma unroll
            for (int c = 0; c < 16; c += 4) {
                float4 v = *reinterpret_cast<const float4*>(&sm.O[r][c0 + c]);
                v.x *= rs; v.y *= rs; v.z *= rs; v.w *= rs;
                *reinterpret_cast<float4*>(&sm.O[r][c0 + c]) = v;
            }
            __syncwarp();

            wmma::fragment<wmma::accumulator, 16, 16, 16, float> p0, p1;
            wmma::load_matrix_sync(p0, &sm.O[wr*16][wc*32],      SF, wmma::mem_row_major);
            wmma::load_matrix_sync(p1, &sm.O[wr*16][wc*32 + 16], SF, wmma::mem_row_major);
            #pragma unroll
            for (int ks = 0; ks < 4; ks++) {
                int kk = ks * 16;
                wmma::fragment<wmma::matrix_a, 16, 16, 16, half, wmma::row_major> ah;
                wmma::fragment<wmma::matrix_b, 16, 16, 16, half, wmma::row_major> bh0, bh1;
                wmma::load_matrix_sync(ah, &sm.Ph[wr*16][kk], SB);
                wmma::load_matrix_sync(bh0, &sm.Vh[kk][wc*32], SB);
                wmma::load_matrix_sync(bh1, &sm.Vh[kk][wc*32+16], SB);
                wmma::mma_sync(p0, ah, bh0, p0);
                wmma::mma_sync(p1, ah, bh1, p1);
            }
            wmma::store_matrix_sync(&sm.O[wr*16][wc*32],      p0, SF, wmma::mem_row_major);
            wmma::store_matrix_sync(&sm.O[wr*16][wc*32 + 16], p1, SF, wmma::mem_row_major);
        }
        __syncthreads();
    }

    // epilogue: normalize, write fp16 hi to [tok][DD]
    {
        float inv = 1.0f / sm.l_s[srow];
        size_t gbase = (size_t)(b*SS + q0 + srow) * DD + h*HD + cb;
        #pragma unroll
        for (int c = 0; c < 16; c += 2) {
            float f0 = sm.O[srow][cb + c] * inv;
            float f1 = sm.O[srow][cb + c + 1] * inv;
            *reinterpret_cast<__half2*>(&ohi[gbase + c]) = __floats2half2_rn(f0, f1);
        }
    }
}

// ===========================================================================
extern "C" void kernel_launch(void* const* d_in, const int* in_sizes, int n_in,
                              void* d_out, int out_size) {
    const float* x     = (const float*)d_in[0];
    const float* W_qkv = (const float*)d_in[1];
    const float* b_qkv = (const float*)d_in[2];
    const float* W_out = (const float*)d_in[3];
    const float* b_out = (const float*)d_in[4];
    float* out = (float*)d_out;

    __half* qhi;
    __half* qlo;
    __half* xh;
    __half* wqh;
    __half* wql;
    __half* woh;
    __half* wol;
    __half* oh;
    cudaGetSymbolAddress((void**)&qhi, g_qkv_hi);
    cudaGetSymbolAddress((void**)&qlo, g_qkv_lo);
    cudaGetSymbolAddress((void**)&xh, g_xh);
    cudaGetSymbolAddress((void**)&wqh, g_wqh);
    cudaGetSymbolAddress((void**)&wql, g_wql);
    cudaGetSymbolAddress((void**)&woh, g_woh);
    cudaGetSymbolAddress((void**)&wol, g_wol);
    cudaGetSymbolAddress((void**)&oh, g_oh);

    cudaFuncSetAttribute(gemm_ps_kernel,
                         cudaFuncAttributeMaxDynamicSharedMemorySize,
                         GEMM_SMEM_BYTES);
    cudaFuncSetAttribute(attn_wmma_kernel,
                         cudaFuncAttributeMaxDynamicSharedMemorySize,
                         (int)sizeof(AttnSmem));

    // 0) splits: x -> hi only; weights -> hi/lo
    split_hi_kernel<<<(MTOK*DD/4)/256, 256>>>(x, xh);
    split_nobias_kernel<<<(3*DD*DD/4)/256, 256>>>(W_qkv, wqh, wql);
    split_nobias_kernel<<<(DD*DD/4)/256, 256>>>(W_out, woh, wol);

    // 1) QKV projection + bias -> fp16 hi/lo [tok][3D]
    gemm_ps_kernel<<<dim3(3*DD/128, MTOK/128), 256, GEMM_SMEM_BYTES>>>(
        xh, wqh, wql, nullptr, qhi, qlo, b_qkv, MTOK, 3*DD, DD);

    // 2) attention (kv-tile 64, R12 version) -> fp16 hi [tok][DD]
    attn_wmma_kernel<<<dim3(SS/128, HH, BB), 512, sizeof(AttnSmem)>>>(qhi, qlo, oh);

    // 3) output projection + bias -> fp32 out
    gemm_ps_kernel<<<dim3(DD/128, MTOK/128), 256, GEMM_SMEM_BYTES>>>(
        oh, woh, wol, out, nullptr, nullptr, b_out, MTOK, DD, DD);
}

// round 16
// speedup vs baseline: 4.2582x; 1.0310x over previous
#include <cuda_runtime.h>
#include <cuda_fp16.h>
#include <cuda_pipeline.h>
#include <mma.h>
#include <math.h>

using namespace nvcuda;

#define BB 2
#define SS 2048
#define DD 1024
#define HH 16
#define HD 64
#define MTOK (BB*SS)

// Scratch (allocation-free rule: __device__ globals)
__device__ __half g_qkv_hi[BB*SS*3*DD];
__device__ __half g_qkv_lo[BB*SS*3*DD];
__device__ __half g_xh[MTOK*DD];
__device__ __half g_wqh[3*DD*DD];
__device__ __half g_wql[3*DD*DD];
__device__ __half g_woh[DD*DD];
__device__ __half g_wol[DD*DD];
__device__ __half g_oh[MTOK*DD];

// ===========================================================================
// split kernels
// ===========================================================================
__global__ void split_nobias_kernel(const float* __restrict__ in,
                                    __half* __restrict__ hi,
                                    __half* __restrict__ lo) {
    int idx = blockIdx.x * blockDim.x + threadIdx.x;
    float4 v = reinterpret_cast<const float4*>(in)[idx];
    __half2 h2[2];
    __half2 l2[2];
    #pragma unroll
    for (int u = 0; u < 4; u++) {
        float f = (&v.x)[u];
        __half h = __float2half_rn(f);
        ((__half*)h2)[u] = h;
        ((__half*)l2)[u] = __float2half_rn(f - __half2float(h));
    }
    reinterpret_cast<__half2*>(hi)[idx*2]   = h2[0];
    reinterpret_cast<__half2*>(hi)[idx*2+1] = h2[1];
    reinterpret_cast<__half2*>(lo)[idx*2]   = l2[0];
    reinterpret_cast<__half2*>(lo)[idx*2+1] = l2[1];
}

__global__ void split_hi_kernel(const float* __restrict__ in,
                                __half* __restrict__ hi) {
    int idx = blockIdx.x * blockDim.x + threadIdx.x;
    float4 v = reinterpret_cast<const float4*>(in)[idx];
    __half2 h2[2];
    h2[0] = __floats2half2_rn(v.x, v.y);
    h2[1] = __floats2half2_rn(v.z, v.w);
    reinterpret_cast<__half2*>(hi)[idx*2]   = h2[0];
    reinterpret_cast<__half2*>(hi)[idx*2+1] = h2[1];
}

// ===========================================================================
// GEMM: C[M,N] = Ah[M,K] @ (Bh+Bl)[N,K]^T + bias  (2-term fp16 split),
// pipelined 2-stage, BK=64. CTA tile 128x128, 256 threads, 8 warps.
// ===========================================================================
#define GSTR 72
#define CST 132

struct GemmSmem {
    __half Ah[2][128][GSTR];
    __half Bh[2][128][GSTR];
    __half Bl[2][128][GSTR];
};

// sizeof(GemmSmem) = 110592 > epilogue staging (128*CST*4 = 67584)
#define GEMM_SMEM_BYTES ((int)sizeof(GemmSmem))

__device__ __forceinline__ void gemm_issue_stage(
        GemmSmem* sm, int s, int k0,
        const __half* Agh,
        const __half* Bgh, const __half* Bgl,
        int row0, int col0, int K, int tid) {
    #pragma unroll
    for (int c = tid; c < 1024; c += 256) {
        int r = c >> 3;
        int o = (c & 7) * 8;
        size_t ga = (size_t)(row0 + r) * K + k0 + o;
        size_t gb = (size_t)(col0 + r) * K + k0 + o;
        __pipeline_memcpy_async(&sm->Ah[s][r][o], &Agh[ga], 16);
        __pipeline_memcpy_async(&sm->Bh[s][r][o], &Bgh[gb], 16);
        __pipeline_memcpy_async(&sm->Bl[s][r][o], &Bgl[gb], 16);
    }
    __pipeline_commit();
}

__global__ __launch_bounds__(256, 2)
void gemm_ps_kernel(const __half* __restrict__ Agh,
                    const __half* __restrict__ Bgh,
                    const __half* __restrict__ Bgl,
                    float* __restrict__ Cf32,
                    __half* __restrict__ Chi,
                    __half* __restrict__ Clo,
                    const float* __restrict__ bias,
                    int M, int N, int K) {
    extern __shared__ char smem_raw[];
    GemmSmem* sm = reinterpret_cast<GemmSmem*>(smem_raw);

    const int tid = threadIdx.x;
    const int warp = tid >> 5;
    const int wr = warp >> 1;
    const int wc = warp & 1;
    const int row0 = blockIdx.y * 128;
    const int col0 = blockIdx.x * 128;
    const int nk = K / 64;

    wmma::fragment<wmma::accumulator, 16, 16, 16, float> acc[2][4];
    #pragma unroll
    for (int i = 0; i < 2; i++) {
        #pragma unroll
        for (int j = 0; j < 4; j++) {
            wmma::fill_fragment(acc[i][j], 0.0f);
        }
    }

    gemm_issue_stage(sm, 0, 0, Agh, Bgh, Bgl, row0, col0, K, tid);

    for (int kt = 0; kt < nk; kt++) {
        if (kt + 1 < nk) {
            gemm_issue_stage(sm, (kt + 1) & 1, (kt + 1) * 64,
                             Agh, Bgh, Bgl, row0, col0, K, tid);
            __pipeline_wait_prior(1);
        } else {
            __pipeline_wait_prior(0);
        }
        __syncthreads();

        const int s = kt & 1;
        #pragma unroll
        for (int kk = 0; kk < 64; kk += 16) {
            wmma::fragment<wmma::matrix_a, 16, 16, 16, half, wmma::row_major> ah[2];
            wmma::load_matrix_sync(ah[0], &sm->Ah[s][wr*32][kk], GSTR);
            wmma::load_matrix_sync(ah[1], &sm->Ah[s][wr*32 + 16][kk], GSTR);
            #pragma unroll
            for (int jp = 0; jp < 2; jp++) {
                const int j0 = jp * 2;
                const int j1 = j0 + 1;
                wmma::fragment<wmma::matrix_b, 16, 16, 16, half, wmma::col_major> bh0, bh1, bl0, bl1;
                wmma::load_matrix_sync(bh0, &sm->Bh[s][wc*64 + j0*16][kk], GSTR);
                wmma::load_matrix_sync(bh1, &sm->Bh[s][wc*64 + j1*16][kk], GSTR);
                wmma::load_matrix_sync(bl0, &sm->Bl[s][wc*64 + j0*16][kk], GSTR);
                wmma::load_matrix_sync(bl1, &sm->Bl[s][wc*64 + j1*16][kk], GSTR);
                // interleaved: same-acc MMAs are 4 apart
                wmma::mma_sync(acc[0][j0], ah[0], bh0, acc[0][j0]);
                wmma::mma_sync(acc[1][j0], ah[1], bh0, acc[1][j0]);
                wmma::mma_sync(acc[0][j1], ah[0], bh1, acc[0][j1]);
                wmma::mma_sync(acc[1][j1], ah[1], bh1, acc[1][j1]);
                wmma::mma_sync(acc[0][j0], ah[0], bl0, acc[0][j0]);
                wmma::mma_sync(acc[1][j0], ah[1], bl0, acc[1][j0]);
                wmma::mma_sync(acc[0][j1], ah[0], bl1, acc[0][j1]);
                wmma::mma_sync(acc[1][j1], ah[1], bl1, acc[1][j1]);
            }
        }
        __syncthreads();
    }

    // ---- fused epilogue: stage acc in smem, add bias, write out ----
    float* stp = reinterpret_cast<float*>(smem_raw);
    #pragma unroll
    for (int i = 0; i < 2; i++) {
        #pragma unroll
        for (int j = 0; j < 4; j++) {
            wmma::store_matrix_sync(&stp[(size_t)(wr*32 + i*16) * CST + wc*64 + j*16],
                                    acc[i][j], CST, wmma::mem_row_major);
        }
    }
    __syncthreads();

    if (Cf32 != nullptr) {
        for (int t = tid; t < 128*32; t += 256) {
            int r = t >> 5;
            int c4 = (t & 31) * 4;
            float4 v = *reinterpret_cast<const float4*>(&stp[r*CST + c4]);
            float4 bv = *reinterpret_cast<const float4*>(&bias[col0 + c4]);
            v.x += bv.x; v.y += bv.y; v.z += bv.z; v.w += bv.w;
            *reinterpret_cast<float4*>(&Cf32[(size_t)(row0 + r) * N + col0 + c4]) = v;
        }
    } else {
        for (int t = tid; t < 128*32; t += 256) {
            int r = t >> 5;
            int c4 = (t & 31) * 4;
            float4 v = *reinterpret_cast<const float4*>(&stp[r*CST + c4]);
            float4 bv = *reinterpret_cast<const float4*>(&bias[col0 + c4]);
            float f0 = v.x + bv.x;
            float f1 = v.y + bv.y;
            float f2 = v.z + bv.z;
            float f3 = v.w + bv.w;
            __half2 h0 = __floats2half2_rn(f0, f1);
            __half2 h1 = __floats2half2_rn(f2, f3);
            __half2 l0 = __floats2half2_rn(f0 - __half2float(h0.x),
                                           f1 - __half2float(h0.y));
            __half2 l1 = __floats2half2_rn(f2 - __half2float(h1.x),
                                           f3 - __half2float(h1.y));
            size_t g = (size_t)(row0 + r) * N + col0 + c4;
            *reinterpret_cast<__half2*>(&Chi[g])     = h0;
            *reinterpret_cast<__half2*>(&Chi[g + 2]) = h1;
            *reinterpret_cast<__half2*>(&Clo[g])     = l0;
            *reinterpret_cast<__half2*>(&Clo[g + 2]) = l1;
        }
    }
}

// ===========================================================================
// Tensor-core flash attention. Q-tile 128, kv-tile 64, 512 threads.
// K/V double-buffered via cp.async (prefetch next tile during compute).
// QK^T 2-term, P raw fp16 from h2exp2, PV single-term fp16 into smem O.
// ===========================================================================
#define SB 72
#define SF 68

struct AttnSmem {
    __half Qh[128][SB];
    __half Kh[2][64][SB];
    __half Kl[2][64][SB];
    __half Vh[2][64][SB];
    __half Ph[128][SB];
    float S[128][SF];
    float O[128][SF];
    float m_s[128];
    float l_s[128];
    float resc[128];
};

__device__ __forceinline__ void attn_issue_kv(
        AttnSmem* sm, int s, int k0,
        const __half* qhi, const __half* qlo,
        int b, int h, int tid) {
    #pragma unroll
    for (int t = tid; t < 64*8; t += 512) {
        int r = t >> 3;
        int c8 = (t & 7) * 8;
        size_t base = (size_t)(b*SS + k0 + r) * (3*DD) + h*HD + c8;
        __pipeline_memcpy_async(&sm->Kh[s][r][c8], &qhi[base + DD], 16);
        __pipeline_memcpy_async(&sm->Kl[s][r][c8], &qlo[base + DD], 16);
        __pipeline_memcpy_async(&sm->Vh[s][r][c8], &qhi[base + 2*DD], 16);
    }
    __pipeline_commit();
}

__global__ __launch_bounds__(512)
void attn_wmma_kernel(const __half* __restrict__ qhi,
                      const __half* __restrict__ qlo,
                      __half* __restrict__ ohi) {
    extern __shared__ char smem_raw[];
    AttnSmem& sm = *reinterpret_cast<AttnSmem*>(smem_raw);

    const int qt = gridDim.x - 1 - blockIdx.x;
    const int h  = blockIdx.y;
    const int b  = blockIdx.z;
    const int tid = threadIdx.x;
    const int warp = tid >> 5;
    const int lane = tid & 31;
    const int wr = warp >> 1;
    const int wc = warp & 1;
    const int q0 = qt * 128;
    const float CSC = 0.18033688011112042f;   // 0.125 * log2(e)
    const int nkt  = 2*qt + 2;

    // prefetch first K/V tile, then load Q / init O while it flies
    attn_issue_kv(&sm, 0, 0, qhi, qlo, b, h, tid);

    for (int t = tid; t < 128*8; t += 512) {
        int r = t >> 3;
        int c8 = (t & 7) * 8;
        size_t g = (size_t)(b*SS + q0 + r) * (3*DD) + h*HD + c8;
        *reinterpret_cast<uint4*>(&sm.Qh[r][c8]) = *reinterpret_cast<const uint4*>(&qhi[g]);
    }
    for (int t = tid; t < 128*16; t += 512) {
        int r = t >> 4;
        int c4 = (t & 15) * 4;
        *reinterpret_cast<float4*>(&sm.O[r][c4]) = make_float4(0.f, 0.f, 0.f, 0.f);
    }
    if (tid < 128) {
        sm.m_s[tid] = -1e30f;
        sm.l_s[tid] = 0.0f;
    }

    const int srow = tid >> 2;
    const int sq   = tid & 3;
    const int cb   = sq * 16;

    for (int kt = 0; kt < nkt; kt++) {
        const int k0 = kt * 64;
        const int s = kt & 1;

        if (kt + 1 < nkt) {
            attn_issue_kv(&sm, (kt + 1) & 1, (kt + 1) * 64, qhi, qlo, b, h, tid);
            __pipeline_wait_prior(1);
        } else {
            __pipeline_wait_prior(0);
        }
        __syncthreads();

        // ---- S = Qh @ (Kh + Kl)^T ----
        {
            wmma::fragment<wmma::accumulator, 16, 16, 16, float> s0, s1;
            wmma::fill_fragment(s0, 0.0f);
            wmma::fill_fragment(s1, 0.0f);
            #pragma unroll
            for (int ks = 0; ks < 4; ks++) {
                int kk = ks * 16;
                wmma::fragment<wmma::matrix_a, 16, 16, 16, half, wmma::row_major> ah;
                wmma::fragment<wmma::matrix_b, 16, 16, 16, half, wmma::col_major> bh0, bh1, bl0, bl1;
                wmma::load_matrix_sync(ah, &sm.Qh[wr*16][kk], SB);
                wmma::load_matrix_sync(bh0, &sm.Kh[s][wc*32][kk], SB);
                wmma::load_matrix_sync(bh1, &sm.Kh[s][wc*32+16][kk], SB);
                wmma::load_matrix_sync(bl0, &sm.Kl[s][wc*32][kk], SB);
                wmma::load_matrix_sync(bl1, &sm.Kl[s][wc*32+16][kk], SB);
                wmma::mma_sync(s0, ah, bh0, s0);
                wmma::mma_sync(s1, ah, bh1, s1);
                wmma::mma_sync(s0, ah, bl0, s0);
                wmma::mma_sync(s1, ah, bl1, s1);
            }
            wmma::store_matrix_sync(&sm.S[wr*16][wc*32],      s0, SF, wmma::mem_row_major);
            wmma::store_matrix_sync(&sm.S[wr*16][wc*32 + 16], s1, SF, wmma::mem_row_major);
        }
        __syncthreads();

        // ---- base-2 online softmax; P stored as raw fp16 (h2exp2 output) ----
        {
            const bool diag = (kt >= 2*qt);
            float sv[16];
            float mloc = -1e30f;
            #pragma unroll
            for (int c4 = 0; c4 < 4; c4++) {
                float4 v = *reinterpret_cast<const float4*>(&sm.S[srow][cb + c4*4]);
                sv[c4*4+0] = v.x * CSC;
                sv[c4*4+1] = v.y * CSC;
                sv[c4*4+2] = v.z * CSC;
                sv[c4*4+3] = v.w * CSC;
            }
            #pragma unroll
            for (int c = 0; c < 16; c++) {
                if (diag && (k0 + cb + c > q0 + srow)) {
                    sv[c] = -1e30f;
                }
                mloc = fmaxf(mloc, sv[c]);
            }
            mloc = fmaxf(mloc, __shfl_xor_sync(0xFFFFFFFF, mloc, 1));
            mloc = fmaxf(mloc, __shfl_xor_sync(0xFFFFFFFF, mloc, 2));
            float mold = sm.m_s[srow];
            float nm = fmaxf(mold, mloc);
            float ls = 0.0f;
            #pragma unroll
            for (int c = 0; c < 16; c += 2) {
                __half2 dh = __floats2half2_rn(sv[c] - nm, sv[c+1] - nm);
                __half2 p2 = h2exp2(dh);
                *reinterpret_cast<__half2*>(&sm.Ph[srow][cb + c]) = p2;
                float2 pf = __half22float2(p2);
                ls += pf.x + pf.y;
            }
            ls += __shfl_xor_sync(0xFFFFFFFF, ls, 1);
            ls += __shfl_xor_sync(0xFFFFFFFF, ls, 2);
            if (sq == 0) {
                float rs = exp2f(mold - nm);
                sm.resc[srow] = rs;
                sm.l_s[srow] = sm.l_s[srow] * rs + ls;
                sm.m_s[srow] = nm;
            }
        }
        __syncthreads();

        // ---- PV: single-term fp16, accumulate directly into O ----
        {
            int r = wr*16 + (lane >> 1);
            int c0 = wc*32 + (lane & 1) * 16;
            float rs = sm.resc[r];
            #pragma unroll
            for (int c = 0; c < 16; c += 4) {
                float4 v = *reinterpret_cast<const float4*>(&sm.O[r][c0 + c]);
                v.x *= rs; v.y *= rs; v.z *= rs; v.w *= rs;
                *reinterpret_cast<float4*>(&sm.O[r][c0 + c]) = v;
            }
            __syncwarp();

            wmma::fragment<wmma::accumulator, 16, 16, 16, float> p0, p1;
            wmma::load_matrix_sync(p0, &sm.O[wr*16][wc*32],      SF, wmma::mem_row_major);
            wmma::load_matrix_sync(p1, &sm.O[wr*16][wc*32 + 16], SF, wmma::mem_row_major);
            #pragma unroll
            for (int ks = 0; ks < 4; ks++) {
                int kk = ks * 16;
                wmma::fragment<wmma::matrix_a, 16, 16, 16, half, wmma::row_major> ah;
                wmma::fragment<wmma::matrix_b, 16, 16, 16, half, wmma::row_major> bh0, bh1;
                wmma::load_matrix_sync(ah, &sm.Ph[wr*16][kk], SB);
                wmma::load_matrix_sync(bh0, &sm.Vh[s][kk][wc*32], SB);
                wmma::load_matrix_sync(bh1, &sm.Vh[s][kk][wc*32+16], SB);
                wmma::mma_sync(p0, ah, bh0, p0);
                wmma::mma_sync(p1, ah, bh1, p1);
            }
            wmma::store_matrix_sync(&sm.O[wr*16][wc*32],      p0, SF, wmma::mem_row_major);
            wmma::store_matrix_sync(&sm.O[wr*16][wc*32 + 16], p1, SF, wmma::mem_row_major);
        }
        __syncthreads();
    }

    // epilogue: normalize, write fp16 hi to [tok][DD]
    {
        float inv = 1.0f / sm.l_s[srow];
        size_t gbase = (size_t)(b*SS + q0 + srow) * DD + h*HD + cb;
        #pragma unroll
        for (int c = 0; c < 16; c += 2) {
            float f0 = sm.O[srow][cb + c] * inv;
            float f1 = sm.O[srow][cb + c + 1] * inv;
            *reinterpret_cast<__half2*>(&ohi[gbase + c]) = __floats2half2_rn(f0, f1);
        }
    }
}

// ===========================================================================
extern "C" void kernel_launch(void* const* d_in, const int* in_sizes, int n_in,
                              void* d_out, int out_size) {
    const float* x     = (const float*)d_in[0];
    const float* W_qkv = (const float*)d_in[1];
    const float* b_qkv = (const float*)d_in[2];
    const float* W_out = (const float*)d_in[3];
    const float* b_out = (const float*)d_in[4];
    float* out = (float*)d_out;

    __half* qhi;
    __half* qlo;
    __half* xh;
    __half* wqh;
    __half* wql;
    __half* woh;
    __half* wol;
    __half* oh;
    cudaGetSymbolAddress((void**)&qhi, g_qkv_hi);
    cudaGetSymbolAddress((void**)&qlo, g_qkv_lo);
    cudaGetSymbolAddress((void**)&xh, g_xh);
    cudaGetSymbolAddress((void**)&wqh, g_wqh);
    cudaGetSymbolAddress((void**)&wql, g_wql);
    cudaGetSymbolAddress((void**)&woh, g_woh);
    cudaGetSymbolAddress((void**)&wol, g_wol);
    cudaGetSymbolAddress((void**)&oh, g_oh);

    cudaFuncSetAttribute(gemm_ps_kernel,
                         cudaFuncAttributeMaxDynamicSharedMemorySize,
                         GEMM_SMEM_BYTES);
    cudaFuncSetAttribute(attn_wmma_kernel,
                         cudaFuncAttributeMaxDynamicSharedMemorySize,
                         (int)sizeof(AttnSmem));

    // 0) splits: x -> hi only; weights -> hi/lo
    split_hi_kernel<<<(MTOK*DD/4)/256, 256>>>(x, xh);
    split_nobias_kernel<<<(3*DD*DD/4)/256, 256>>>(W_qkv, wqh, wql);
    split_nobias_kernel<<<(DD*DD/4)/256, 256>>>(W_out, woh, wol);

    // 1) QKV projection + bias -> fp16 hi/lo [tok][3D]
    gemm_ps_kernel<<<dim3(3*DD/128, MTOK/128), 256, GEMM_SMEM_BYTES>>>(
        xh, wqh, wql, nullptr, qhi, qlo, b_qkv, MTOK, 3*DD, DD);

    // 2) attention (kv-tile 64, cp.async double-buffered) -> fp16 hi [tok][DD]
    attn_wmma_kernel<<<dim3(SS/128, HH, BB), 512, sizeof(AttnSmem)>>>(qhi, qlo, oh);

    // 3) output projection + bias -> fp32 out
    gemm_ps_kernel<<<dim3(DD/128, MTOK/128), 256, GEMM_SMEM_BYTES>>>(
        oh, woh, wol, out, nullptr, nullptr, b_out, MTOK, DD, DD);
}